// round 1
// baseline (speedup 1.0000x reference)
#include <cuda_runtime.h>
#include <math.h>

// Problem constants
#define PB 8       // batch
#define PL 256     // seq len
#define PD 2048    // d_model
#define PH 8       // heads
#define PDH 256    // head dim
#define PT (PB*PL) // tokens = 2048

// ---------------- scratch (static device arrays; no allocation) ----------------
__device__ float g_Q[PB*PH*PL*PDH];
__device__ float g_K[PB*PH*PL*PDH];
__device__ float g_V[PB*PH*PL*PDH];
__device__ float g_kv[PB*PH*PL*PL];
__device__ float g_pq[PB*PH*PL*PDH];
__device__ float g_pk[PB*PH*PL*PDH];
__device__ float g_Am[PB*PH*PL*PL];
__device__ float g_attn[PT*PD];   // (B,L,D) layout
__device__ float g_o[PT*PD];
__device__ float g_mh[PH*PL];
__device__ float g_cs[PH*PDH];

// ---------------- generic tiled GEMM ----------------
// C = A @ B^T (TRANSB=true) or A @ B (TRANSB=false), fp32.
// BM=BN=128, BK=8, 256 threads, 8x8 microtile. All dims are exact multiples.
#define BM 128
#define BN 128
#define BK 8
#define TM 8
#define TN 8

// EPI: 0 = proj permute (M,N)->(B,H,L,Dh); 1 = plain batched row-major;
//      2 = causal-masked batched; 3 = attn-out (divide by den, scatter to (B,L,D));
//      4 = bias add, plain row-major.
template<int EPI, bool TRANSB>
__global__ __launch_bounds__(256)
void gemm_kernel(const float* __restrict__ Ag, const float* __restrict__ Bg,
                 float* __restrict__ Cg, const float* __restrict__ bias,
                 int M, int N, int Kd, int lda, int ldb,
                 long strideA, long strideB, long strideC)
{
    __shared__ float As[BK][BM];
    __shared__ float Bs[BK][BN];

    const int z  = blockIdx.z;
    const float* A  = Ag + (long)z * strideA;
    const float* Bm = Bg + (long)z * strideB;

    const int m0 = blockIdx.y * BM;
    const int n0 = blockIdx.x * BN;
    const int tid = threadIdx.x;
    const int tx = tid & 15;
    const int ty = tid >> 4;

    float acc[TM][TN];
#pragma unroll
    for (int i = 0; i < TM; i++)
#pragma unroll
        for (int j = 0; j < TN; j++) acc[i][j] = 0.f;

    float den[TM];
#pragma unroll
    for (int i = 0; i < TM; i++) den[i] = 0.f;

    // load coords
    const int arow = tid >> 1;          // 0..127
    const int akq  = (tid & 1) * 4;     // 0 or 4
    const int bkrow = tid >> 5;         // 0..7   (NN path)
    const int bnq   = (tid & 31) * 4;   // 0..124 (NN path)

    for (int k0 = 0; k0 < Kd; k0 += BK) {
        float4 av = *(const float4*)(A + (long)(m0 + arow) * lda + k0 + akq);
        As[akq+0][arow] = av.x;
        As[akq+1][arow] = av.y;
        As[akq+2][arow] = av.z;
        As[akq+3][arow] = av.w;
        if (TRANSB) {
            float4 bv = *(const float4*)(Bm + (long)(n0 + arow) * ldb + k0 + akq);
            Bs[akq+0][arow] = bv.x;
            Bs[akq+1][arow] = bv.y;
            Bs[akq+2][arow] = bv.z;
            Bs[akq+3][arow] = bv.w;
        } else {
            float4 bv = *(const float4*)(Bm + (long)(k0 + bkrow) * ldb + n0 + bnq);
            Bs[bkrow][bnq+0] = bv.x;
            Bs[bkrow][bnq+1] = bv.y;
            Bs[bkrow][bnq+2] = bv.z;
            Bs[bkrow][bnq+3] = bv.w;
        }
        __syncthreads();

#pragma unroll
        for (int kk = 0; kk < BK; kk++) {
            float ra[TM], rb[TN];
#pragma unroll
            for (int i = 0; i < TM; i++) ra[i] = As[kk][ty*TM + i];
#pragma unroll
            for (int j = 0; j < TN; j++) rb[j] = Bs[kk][tx*TN + j];
            if (EPI == 3) {
#pragma unroll
                for (int i = 0; i < TM; i++) den[i] += ra[i];
            }
#pragma unroll
            for (int i = 0; i < TM; i++)
#pragma unroll
                for (int j = 0; j < TN; j++)
                    acc[i][j] = fmaf(ra[i], rb[j], acc[i][j]);
        }
        __syncthreads();
    }

    // epilogue
#pragma unroll
    for (int i = 0; i < TM; i++) {
        const int m = m0 + ty*TM + i;
        if (EPI == 3) {
            const float inv = 1.0f / fmaxf(den[i], 1e-8f);
            const int b = z / PH, h = z % PH;
            float* outr = Cg + ((long)(b*PL + m) * PD) + h*PDH;
#pragma unroll
            for (int j = 0; j < TN; j++) {
                const int n = n0 + tx*TN + j;
                outr[n] = acc[i][j] * inv;
            }
        } else if (EPI == 0) {
            const int b = m >> 8, l = m & 255;
#pragma unroll
            for (int j = 0; j < TN; j++) {
                const int n = n0 + tx*TN + j;
                const int h = n >> 8, d = n & 255;
                Cg[((long)(b*PH + h) * PL + l) * PDH + d] = acc[i][j];
            }
        } else if (EPI == 1) {
            float* cr = Cg + (long)z * strideC + (long)m * N;
#pragma unroll
            for (int j = 0; j < TN; j++) cr[n0 + tx*TN + j] = acc[i][j];
        } else if (EPI == 2) {
            float* cr = Cg + (long)z * strideC + (long)m * N;
#pragma unroll
            for (int j = 0; j < TN; j++) {
                const int n = n0 + tx*TN + j;
                cr[n] = (n <= m) ? acc[i][j] : 0.0f;
            }
        } else { // EPI == 4
            float* cr = Cg + (long)m * N;
#pragma unroll
            for (int j = 0; j < TN; j++) {
                const int n = n0 + tx*TN + j;
                cr[n] = acc[i][j] + bias[n];
            }
        }
    }
}

// ---------------- small kernels ----------------
__global__ void zero_mh_kernel(float* mh) {
    int i = blockIdx.x * blockDim.x + threadIdx.x;
    if (i < PH*PL) mh[i] = 0.f;
}

// mh[h][m] = mean over (b,l) of kv[b,h,l,m]
__global__ void mh_kernel(const float* __restrict__ kv, float* __restrict__ mh) {
    const int h = blockIdx.x, b = blockIdx.y, m = threadIdx.x;
    const float* base = kv + ((long)(b*PH + h) * PL) * PL + m;
    float s = 0.f;
#pragma unroll 4
    for (int l = 0; l < PL; l++) s += base[(long)l * PL];
    atomicAdd(&mh[h*PL + m], s * (1.0f / (float)(PB*PL)));
}

// cs_seq[h] = cs before update h; cs = beta*cs + alpha*mh[h]
__global__ void cs_kernel(const float* __restrict__ mh, float* __restrict__ cs,
                          const float* __restrict__ alpha_p, const float* __restrict__ beta_p) {
    const int d = threadIdx.x;
    const float a = *alpha_p, bt = *beta_p;
    float c = 0.f;
    for (int h = 0; h < PH; h++) {
        cs[h*PDH + d] = c;
        c = bt * c + a * mh[h*PL + d];
    }
}

// pq = phi(Q * (cs + alpha*(kv - cs))), pk = phi(K); phi(x) = x>0 ? x+1 : exp(x)
__global__ void phi_kernel(const float* __restrict__ Q, const float* __restrict__ K,
                           const float* __restrict__ kv, const float* __restrict__ cs,
                           float* __restrict__ pq, float* __restrict__ pk,
                           const float* __restrict__ alpha_p) {
    const long idx = (long)blockIdx.x * blockDim.x + threadIdx.x;
    const float a = *alpha_p;
    const int h = (int)((idx >> 16) & 7);
    const int d = (int)(idx & 255);
    const float c = cs[h*PDH + d];
    const float qm = Q[idx] * (c + a * (kv[idx] - c));
    pq[idx] = qm > 0.f ? qm + 1.f : __expf(qm);
    const float kk = K[idx];
    pk[idx] = kk > 0.f ? kk + 1.f : __expf(kk);
}

// residual + layernorm: one block per token, 256 threads, 8 elems/thread
__global__ void ln_kernel(const float* __restrict__ q, const float* __restrict__ o,
                          const float* __restrict__ g, const float* __restrict__ be,
                          float* __restrict__ out) {
    const int t = blockIdx.x;
    const int tid = threadIdx.x;
    __shared__ float red[256];
    const float* xq = q + (long)t * PD;
    const float* xo = o + (long)t * PD;
    float x[8];
    float s = 0.f;
#pragma unroll
    for (int i = 0; i < 8; i++) {
        x[i] = xq[tid + i*256] + xo[tid + i*256];
        s += x[i];
    }
    red[tid] = s; __syncthreads();
    for (int st = 128; st > 0; st >>= 1) {
        if (tid < st) red[tid] += red[tid + st];
        __syncthreads();
    }
    const float mu = red[0] * (1.0f / PD);
    __syncthreads();
    float v = 0.f;
#pragma unroll
    for (int i = 0; i < 8; i++) { const float dd = x[i] - mu; v += dd*dd; }
    red[tid] = v; __syncthreads();
    for (int st = 128; st > 0; st >>= 1) {
        if (tid < st) red[tid] += red[tid + st];
        __syncthreads();
    }
    const float inv = rsqrtf(red[0] * (1.0f / PD) + 1e-5f);
#pragma unroll
    for (int i = 0; i < 8; i++) {
        const int c = tid + i*256;
        out[(long)t*PD + c] = (x[i] - mu) * inv * g[c] + be[c];
    }
}

// ---------------- launch ----------------
extern "C" void kernel_launch(void* const* d_in, const int* in_sizes, int n_in,
                              void* d_out, int out_size) {
    const float* query = (const float*)d_in[0];
    const float* key   = (const float*)d_in[1];
    const float* value = (const float*)d_in[2];
    const float* Wq    = (const float*)d_in[3];
    const float* Wk    = (const float*)d_in[4];
    const float* Wv    = (const float*)d_in[5];
    const float* Wo    = (const float*)d_in[6];
    const float* bo    = (const float*)d_in[7];
    const float* ln_g  = (const float*)d_in[8];
    const float* ln_b  = (const float*)d_in[9];
    const float* alpha = (const float*)d_in[10];
    const float* beta  = (const float*)d_in[11];
    float* out = (float*)d_out;

    float *Q, *K, *V, *kv, *pq, *pk, *Am, *attn, *o, *mh, *cs;
    cudaGetSymbolAddress((void**)&Q,  g_Q);
    cudaGetSymbolAddress((void**)&K,  g_K);
    cudaGetSymbolAddress((void**)&V,  g_V);
    cudaGetSymbolAddress((void**)&kv, g_kv);
    cudaGetSymbolAddress((void**)&pq, g_pq);
    cudaGetSymbolAddress((void**)&pk, g_pk);
    cudaGetSymbolAddress((void**)&Am, g_Am);
    cudaGetSymbolAddress((void**)&attn, g_attn);
    cudaGetSymbolAddress((void**)&o,  g_o);
    cudaGetSymbolAddress((void**)&mh, g_mh);
    cudaGetSymbolAddress((void**)&cs, g_cs);

    dim3 blk(256);
    dim3 gProj(PD/BN, PT/BM, 1);          // 16 x 16
    dim3 gBat(PL/BN, PL/BM, PB*PH);       // 2 x 2 x 64

    // 1. projections (X @ W^T) with permute epilogue to (B,H,L,Dh)
    gemm_kernel<0,true><<<gProj, blk>>>(query, Wq, Q, nullptr, PT, PD, PD, PD, PD, 0, 0, 0);
    gemm_kernel<0,true><<<gProj, blk>>>(key,   Wk, K, nullptr, PT, PD, PD, PD, PD, 0, 0, 0);
    gemm_kernel<0,true><<<gProj, blk>>>(value, Wv, V, nullptr, PT, PD, PD, PD, PD, 0, 0, 0);

    // 2. kv = K @ V^T per (b,h)
    gemm_kernel<1,true><<<gBat, blk>>>(K, V, kv, nullptr, PL, PL, PDH, PDH, PDH,
                                       (long)PL*PDH, (long)PL*PDH, (long)PL*PL);

    // 3. mh = mean over (b,l) of kv
    zero_mh_kernel<<<(PH*PL + 255)/256, 256>>>(mh);
    mh_kernel<<<dim3(PH, PB), 256>>>(kv, mh);

    // 4. cs scan over heads
    cs_kernel<<<1, 256>>>(mh, cs, alpha, beta);

    // 5. pq/pk elementwise
    phi_kernel<<<(PB*PH*PL*PDH)/1024, 1024>>>(Q, K, kv, cs, pq, pk, alpha);

    // 6. A = tril(pq @ pk^T) per (b,h)
    gemm_kernel<2,true><<<gBat, blk>>>(pq, pk, Am, nullptr, PL, PL, PDH, PDH, PDH,
                                       (long)PL*PDH, (long)PL*PDH, (long)PL*PL);

    // 7. attn = (A @ V) / rowsum(A), scattered to (B,L,D)
    gemm_kernel<3,false><<<gBat, blk>>>(Am, V, attn, nullptr, PL, PDH, PL, PL, PDH,
                                        (long)PL*PL, (long)PL*PDH, 0);

    // 8. o = attn @ Wo^T + bo
    gemm_kernel<4,true><<<gProj, blk>>>(attn, Wo, o, bo, PT, PD, PD, PD, PD, 0, 0, 0);

    // 9. residual + layernorm
    ln_kernel<<<PT, 256>>>(query, o, ln_g, ln_b, out);
}

// round 2
// speedup vs baseline: 2.9743x; 2.9743x over previous
#include <cuda_runtime.h>
#include <math.h>
#include <stdint.h>

// Problem constants
#define PB 8       // batch
#define PL 256     // seq len
#define PD 2048    // d_model
#define PH 8       // heads
#define PDH 256    // head dim
#define PT (PB*PL) // tokens = 2048

// ---------------- scratch (static device arrays; no allocation) ----------------
__device__ float g_Q[PB*PH*PL*PDH];
__device__ float g_K[PB*PH*PL*PDH];
__device__ float g_V[PB*PH*PL*PDH];
__device__ float g_kv[PB*PH*PL*PL];
__device__ float g_pq[PB*PH*PL*PDH];
__device__ float g_pk[PB*PH*PL*PDH];
__device__ float g_Am[PB*PH*PL*PL];
__device__ float g_attn[PT*PD];   // (B,L,D) layout
__device__ float g_o[PT*PD];
__device__ float g_mh[PH*PL];
__device__ float g_cs[PH*PDH];

// ---------------- tf32 helpers ----------------
__device__ __forceinline__ uint32_t f2tf(float x) {
    uint32_t r;
    asm("cvt.rna.tf32.f32 %0, %1;" : "=r"(r) : "f"(x));
    return r;
}
__device__ __forceinline__ uint4 f4tf(const float4 v) {
    uint4 r;
    r.x = f2tf(v.x); r.y = f2tf(v.y); r.z = f2tf(v.z); r.w = f2tf(v.w);
    return r;
}

// ---------------- tf32 tensor-core GEMM ----------------
// C = A @ B^T (TRANSB) or A @ B.  BM=BN=128, BK=16, 256 threads (8 warps),
// warp tile 64x32 via mma.sync.m16n8k8.tf32, double-buffered smem.
// EPI: 0 = proj permute (M,N)->(B,H,L,Dh); 1 = plain batched row-major;
//      2 = causal-masked batched; 3 = attn-out (divide by rowsum(A), scatter to (B,L,D));
//      4 = bias add, plain row-major.
#define BK 16
#define ASTR 20      // smem row stride (floats) for [row][k] tiles -> conflict-free frag loads
#define BSTR_NN 136  // smem row stride for [k][n] tile -> conflict-free frag loads

template<int EPI, bool TRANSB>
__global__ __launch_bounds__(256)
void mma_gemm(const float* __restrict__ Ag, const float* __restrict__ Bg,
              float* __restrict__ Cg, const float* __restrict__ bias,
              int N, int Kd, int lda, int ldb,
              long strideA, long strideB, long strideC)
{
    constexpr int BSZ = TRANSB ? 128*ASTR : BK*BSTR_NN;
    __shared__ uint32_t As[2][128*ASTR];
    __shared__ uint32_t Bs[2][BSZ];

    const int tid = threadIdx.x;
    const int lane = tid & 31;
    const int warpId = tid >> 5;
    const int g = lane >> 2;      // groupID
    const int t = lane & 3;       // threadID_in_group
    const int warpM = warpId >> 2;   // 0..1  -> 64 rows
    const int warpN = warpId & 3;    // 0..3  -> 32 cols
    const int m0 = blockIdx.y * 128;
    const int n0 = blockIdx.x * 128;
    const int z  = blockIdx.z;
    const float* A  = Ag + (long)z * strideA;
    const float* Bm = Bg + (long)z * strideB;

    // global->smem staging coords
    const int aRow = tid >> 2;          // 0..63 (and +64)
    const int aC4  = (tid & 3) * 4;     // 0,4,8,12
    const int bRowNN = tid >> 5;        // 0..7 (and +8)
    const int bC4NN  = (tid & 31) * 4;  // 0..124

    float acc[4][4][4];
#pragma unroll
    for (int mt = 0; mt < 4; mt++)
#pragma unroll
        for (int nt = 0; nt < 4; nt++)
#pragma unroll
            for (int i = 0; i < 4; i++) acc[mt][nt][i] = 0.f;

    float denL[4] = {0.f,0.f,0.f,0.f};
    float denH[4] = {0.f,0.f,0.f,0.f};

    uint4 ra0, ra1, rb0, rb1;

    // prologue: load k-tile 0 into buffer 0
    {
        ra0 = f4tf(*(const float4*)(A + (long)(m0 + aRow)      * lda + aC4));
        ra1 = f4tf(*(const float4*)(A + (long)(m0 + aRow + 64) * lda + aC4));
        if (TRANSB) {
            rb0 = f4tf(*(const float4*)(Bm + (long)(n0 + aRow)      * ldb + aC4));
            rb1 = f4tf(*(const float4*)(Bm + (long)(n0 + aRow + 64) * ldb + aC4));
        } else {
            rb0 = f4tf(*(const float4*)(Bm + (long)(bRowNN)     * ldb + n0 + bC4NN));
            rb1 = f4tf(*(const float4*)(Bm + (long)(bRowNN + 8) * ldb + n0 + bC4NN));
        }
        *(uint4*)&As[0][aRow*ASTR + aC4]        = ra0;
        *(uint4*)&As[0][(aRow+64)*ASTR + aC4]   = ra1;
        if (TRANSB) {
            *(uint4*)&Bs[0][aRow*ASTR + aC4]      = rb0;
            *(uint4*)&Bs[0][(aRow+64)*ASTR + aC4] = rb1;
        } else {
            *(uint4*)&Bs[0][bRowNN*BSTR_NN + bC4NN]     = rb0;
            *(uint4*)&Bs[0][(bRowNN+8)*BSTR_NN + bC4NN] = rb1;
        }
    }
    __syncthreads();

    int buf = 0;
    for (int k0 = 0; k0 < Kd; k0 += BK) {
        const bool has = (k0 + BK) < Kd;
        if (has) {
            const int kn = k0 + BK;
            ra0 = f4tf(*(const float4*)(A + (long)(m0 + aRow)      * lda + kn + aC4));
            ra1 = f4tf(*(const float4*)(A + (long)(m0 + aRow + 64) * lda + kn + aC4));
            if (TRANSB) {
                rb0 = f4tf(*(const float4*)(Bm + (long)(n0 + aRow)      * ldb + kn + aC4));
                rb1 = f4tf(*(const float4*)(Bm + (long)(n0 + aRow + 64) * ldb + kn + aC4));
            } else {
                rb0 = f4tf(*(const float4*)(Bm + (long)(kn + bRowNN)     * ldb + n0 + bC4NN));
                rb1 = f4tf(*(const float4*)(Bm + (long)(kn + bRowNN + 8) * ldb + n0 + bC4NN));
            }
        }

        // compute on current buffer
#pragma unroll
        for (int kk = 0; kk < BK; kk += 8) {
            uint32_t af[4][4];
#pragma unroll
            for (int mt = 0; mt < 4; mt++) {
                const int rb = (warpM*64 + mt*16 + g) * ASTR + kk + t;
                af[mt][0] = As[buf][rb];
                af[mt][1] = As[buf][rb + 8*ASTR];
                af[mt][2] = As[buf][rb + 4];
                af[mt][3] = As[buf][rb + 8*ASTR + 4];
            }
            uint32_t bfr[4][2];
#pragma unroll
            for (int nt = 0; nt < 4; nt++) {
                const int cb = warpN*32 + nt*8 + g;
                if (TRANSB) {
                    bfr[nt][0] = Bs[buf][cb*ASTR + kk + t];
                    bfr[nt][1] = Bs[buf][cb*ASTR + kk + t + 4];
                } else {
                    bfr[nt][0] = Bs[buf][(kk + t)*BSTR_NN + cb];
                    bfr[nt][1] = Bs[buf][(kk + t + 4)*BSTR_NN + cb];
                }
            }
            if (EPI == 3) {
#pragma unroll
                for (int mt = 0; mt < 4; mt++) {
                    denL[mt] += __uint_as_float(af[mt][0]) + __uint_as_float(af[mt][2]);
                    denH[mt] += __uint_as_float(af[mt][1]) + __uint_as_float(af[mt][3]);
                }
            }
#pragma unroll
            for (int mt = 0; mt < 4; mt++)
#pragma unroll
                for (int nt = 0; nt < 4; nt++) {
                    asm volatile(
                        "mma.sync.aligned.m16n8k8.row.col.f32.tf32.tf32.f32 "
                        "{%0,%1,%2,%3}, {%4,%5,%6,%7}, {%8,%9}, {%0,%1,%2,%3};\n"
                        : "+f"(acc[mt][nt][0]), "+f"(acc[mt][nt][1]),
                          "+f"(acc[mt][nt][2]), "+f"(acc[mt][nt][3])
                        : "r"(af[mt][0]), "r"(af[mt][1]), "r"(af[mt][2]), "r"(af[mt][3]),
                          "r"(bfr[nt][0]), "r"(bfr[nt][1]));
                }
        }

        if (has) {
            const int nb = buf ^ 1;
            *(uint4*)&As[nb][aRow*ASTR + aC4]        = ra0;
            *(uint4*)&As[nb][(aRow+64)*ASTR + aC4]   = ra1;
            if (TRANSB) {
                *(uint4*)&Bs[nb][aRow*ASTR + aC4]      = rb0;
                *(uint4*)&Bs[nb][(aRow+64)*ASTR + aC4] = rb1;
            } else {
                *(uint4*)&Bs[nb][bRowNN*BSTR_NN + bC4NN]     = rb0;
                *(uint4*)&Bs[nb][(bRowNN+8)*BSTR_NN + bC4NN] = rb1;
            }
        }
        __syncthreads();
        buf ^= 1;
    }

    // ---- epilogue ----
    float invL[4], invH[4];
    if (EPI == 3) {
#pragma unroll
        for (int mt = 0; mt < 4; mt++) {
            float dl = denL[mt], dh = denH[mt];
            dl += __shfl_xor_sync(0xffffffffu, dl, 1);
            dl += __shfl_xor_sync(0xffffffffu, dl, 2);
            dh += __shfl_xor_sync(0xffffffffu, dh, 1);
            dh += __shfl_xor_sync(0xffffffffu, dh, 2);
            invL[mt] = 1.0f / fmaxf(dl, 1e-8f);
            invH[mt] = 1.0f / fmaxf(dh, 1e-8f);
        }
    }

#pragma unroll
    for (int mt = 0; mt < 4; mt++) {
        const int rL = m0 + warpM*64 + mt*16 + g;
        const int rH = rL + 8;
#pragma unroll
        for (int nt = 0; nt < 4; nt++) {
            const int c = n0 + warpN*32 + nt*8 + t*2;
            float2 vL = make_float2(acc[mt][nt][0], acc[mt][nt][1]);
            float2 vH = make_float2(acc[mt][nt][2], acc[mt][nt][3]);
            if (EPI == 0) {
                const int h = c >> 8, d = c & 255;
                {
                    const int b = rL >> 8, l = rL & 255;
                    *(float2*)&Cg[(((long)(b*PH + h))*PL + l)*PDH + d] = vL;
                }
                {
                    const int b = rH >> 8, l = rH & 255;
                    *(float2*)&Cg[(((long)(b*PH + h))*PL + l)*PDH + d] = vH;
                }
            } else if (EPI == 1) {
                float* cz = Cg + (long)z * strideC;
                *(float2*)&cz[(long)rL*N + c] = vL;
                *(float2*)&cz[(long)rH*N + c] = vH;
            } else if (EPI == 2) {
                float* cz = Cg + (long)z * strideC;
                float2 wL = make_float2(c   <= rL ? vL.x : 0.f,
                                        c+1 <= rL ? vL.y : 0.f);
                float2 wH = make_float2(c   <= rH ? vH.x : 0.f,
                                        c+1 <= rH ? vH.y : 0.f);
                *(float2*)&cz[(long)rL*N + c] = wL;
                *(float2*)&cz[(long)rH*N + c] = wH;
            } else if (EPI == 3) {
                const int b = z / PH, h = z % PH;
                float2 wL = make_float2(vL.x*invL[mt], vL.y*invL[mt]);
                float2 wH = make_float2(vH.x*invH[mt], vH.y*invH[mt]);
                *(float2*)&Cg[((long)(b*PL + rL))*PD + h*PDH + c] = wL;
                *(float2*)&Cg[((long)(b*PL + rH))*PD + h*PDH + c] = wH;
            } else { // EPI == 4
                float2 bv = *(const float2*)&bias[c];
                *(float2*)&Cg[(long)rL*N + c] = make_float2(vL.x + bv.x, vL.y + bv.y);
                *(float2*)&Cg[(long)rH*N + c] = make_float2(vH.x + bv.x, vH.y + bv.y);
            }
        }
    }
}

// ---------------- small kernels ----------------
__global__ void zero_mh_kernel(float* mh) {
    int i = blockIdx.x * blockDim.x + threadIdx.x;
    if (i < PH*PL) mh[i] = 0.f;
}

// mh[h][m] = mean over (b,l) of kv[b,h,l,m]
__global__ void mh_kernel(const float* __restrict__ kv, float* __restrict__ mh) {
    const int h = blockIdx.x, b = blockIdx.y, m = threadIdx.x;
    const float* base = kv + ((long)(b*PH + h) * PL) * PL + m;
    float s = 0.f;
#pragma unroll 4
    for (int l = 0; l < PL; l++) s += base[(long)l * PL];
    atomicAdd(&mh[h*PL + m], s * (1.0f / (float)(PB*PL)));
}

// cs_seq[h] = cs before update h; cs = beta*cs + alpha*mh[h]
__global__ void cs_kernel(const float* __restrict__ mh, float* __restrict__ cs,
                          const float* __restrict__ alpha_p, const float* __restrict__ beta_p) {
    const int d = threadIdx.x;
    const float a = *alpha_p, bt = *beta_p;
    float c = 0.f;
    for (int h = 0; h < PH; h++) {
        cs[h*PDH + d] = c;
        c = bt * c + a * mh[h*PL + d];
    }
}

// pq = phi(Q * (cs + alpha*(kv - cs))), pk = phi(K); phi(x) = x>0 ? x+1 : exp(x)
__global__ void phi_kernel(const float* __restrict__ Q, const float* __restrict__ K,
                           const float* __restrict__ kv, const float* __restrict__ cs,
                           float* __restrict__ pq, float* __restrict__ pk,
                           const float* __restrict__ alpha_p) {
    const long idx = (long)blockIdx.x * blockDim.x + threadIdx.x;
    const float a = *alpha_p;
    const int h = (int)((idx >> 16) & 7);
    const int d = (int)(idx & 255);
    const float c = cs[h*PDH + d];
    const float qm = Q[idx] * (c + a * (kv[idx] - c));
    pq[idx] = qm > 0.f ? qm + 1.f : __expf(qm);
    const float kk = K[idx];
    pk[idx] = kk > 0.f ? kk + 1.f : __expf(kk);
}

// residual + layernorm: one block per token, 256 threads, 8 elems/thread
__global__ void ln_kernel(const float* __restrict__ q, const float* __restrict__ o,
                          const float* __restrict__ g, const float* __restrict__ be,
                          float* __restrict__ out) {
    const int tk = blockIdx.x;
    const int tid = threadIdx.x;
    __shared__ float red[256];
    const float* xq = q + (long)tk * PD;
    const float* xo = o + (long)tk * PD;
    float x[8];
    float s = 0.f;
#pragma unroll
    for (int i = 0; i < 8; i++) {
        x[i] = xq[tid + i*256] + xo[tid + i*256];
        s += x[i];
    }
    red[tid] = s; __syncthreads();
    for (int st = 128; st > 0; st >>= 1) {
        if (tid < st) red[tid] += red[tid + st];
        __syncthreads();
    }
    const float mu = red[0] * (1.0f / PD);
    __syncthreads();
    float v = 0.f;
#pragma unroll
    for (int i = 0; i < 8; i++) { const float dd = x[i] - mu; v += dd*dd; }
    red[tid] = v; __syncthreads();
    for (int st = 128; st > 0; st >>= 1) {
        if (tid < st) red[tid] += red[tid + st];
        __syncthreads();
    }
    const float inv = rsqrtf(red[0] * (1.0f / PD) + 1e-5f);
#pragma unroll
    for (int i = 0; i < 8; i++) {
        const int c = tid + i*256;
        out[(long)tk*PD + c] = (x[i] - mu) * inv * g[c] + be[c];
    }
}

// ---------------- launch ----------------
extern "C" void kernel_launch(void* const* d_in, const int* in_sizes, int n_in,
                              void* d_out, int out_size) {
    const float* query = (const float*)d_in[0];
    const float* key   = (const float*)d_in[1];
    const float* value = (const float*)d_in[2];
    const float* Wq    = (const float*)d_in[3];
    const float* Wk    = (const float*)d_in[4];
    const float* Wv    = (const float*)d_in[5];
    const float* Wo    = (const float*)d_in[6];
    const float* bo    = (const float*)d_in[7];
    const float* ln_g  = (const float*)d_in[8];
    const float* ln_b  = (const float*)d_in[9];
    const float* alpha = (const float*)d_in[10];
    const float* beta  = (const float*)d_in[11];
    float* out = (float*)d_out;

    float *Q, *K, *V, *kv, *pq, *pk, *Am, *attn, *o, *mh, *cs;
    cudaGetSymbolAddress((void**)&Q,  g_Q);
    cudaGetSymbolAddress((void**)&K,  g_K);
    cudaGetSymbolAddress((void**)&V,  g_V);
    cudaGetSymbolAddress((void**)&kv, g_kv);
    cudaGetSymbolAddress((void**)&pq, g_pq);
    cudaGetSymbolAddress((void**)&pk, g_pk);
    cudaGetSymbolAddress((void**)&Am, g_Am);
    cudaGetSymbolAddress((void**)&attn, g_attn);
    cudaGetSymbolAddress((void**)&o,  g_o);
    cudaGetSymbolAddress((void**)&mh, g_mh);
    cudaGetSymbolAddress((void**)&cs, g_cs);

    dim3 blk(256);
    dim3 gProj(PD/128, PT/128, 1);          // 16 x 16
    dim3 gBat(PL/128, PL/128, PB*PH);       // 2 x 2 x 64

    // 1. projections (X @ W^T) with permute epilogue to (B,H,L,Dh)
    mma_gemm<0,true><<<gProj, blk>>>(query, Wq, Q, nullptr, PD, PD, PD, PD, 0, 0, 0);
    mma_gemm<0,true><<<gProj, blk>>>(key,   Wk, K, nullptr, PD, PD, PD, PD, 0, 0, 0);
    mma_gemm<0,true><<<gProj, blk>>>(value, Wv, V, nullptr, PD, PD, PD, PD, 0, 0, 0);

    // 2. kv = K @ V^T per (b,h)
    mma_gemm<1,true><<<gBat, blk>>>(K, V, kv, nullptr, PL, PDH, PDH, PDH,
                                    (long)PL*PDH, (long)PL*PDH, (long)PL*PL);

    // 3. mh = mean over (b,l) of kv
    zero_mh_kernel<<<(PH*PL + 255)/256, 256>>>(mh);
    mh_kernel<<<dim3(PH, PB), 256>>>(kv, mh);

    // 4. cs scan over heads
    cs_kernel<<<1, 256>>>(mh, cs, alpha, beta);

    // 5. pq/pk elementwise
    phi_kernel<<<(PB*PH*PL*PDH)/1024, 1024>>>(Q, K, kv, cs, pq, pk, alpha);

    // 6. A = tril(pq @ pk^T) per (b,h)
    mma_gemm<2,true><<<gBat, blk>>>(pq, pk, Am, nullptr, PL, PDH, PDH, PDH,
                                    (long)PL*PDH, (long)PL*PDH, (long)PL*PL);

    // 7. attn = (A @ V) / rowsum(A), scattered to (B,L,D)
    mma_gemm<3,false><<<gBat, blk>>>(Am, V, attn, nullptr, PDH, PL, PL, PDH,
                                     (long)PL*PL, (long)PL*PDH, 0);

    // 8. o = attn @ Wo^T + bo
    mma_gemm<4,true><<<gProj, blk>>>(attn, Wo, o, bo, PD, PD, PD, PD, 0, 0, 0);

    // 9. residual + layernorm
    ln_kernel<<<PT, 256>>>(query, o, ln_g, ln_b, out);
}

// round 4
// speedup vs baseline: 3.3599x; 1.1296x over previous
#include <cuda_runtime.h>
#include <cuda_bf16.h>
#include <math.h>
#include <stdint.h>

// Problem constants
#define PB 8       // batch
#define PL 256     // seq len
#define PD 2048    // d_model
#define PH 8       // heads
#define PDH 256    // head dim
#define PT (PB*PL) // tokens = 2048

// ---------------- scratch ----------------
__device__ float g_Q[PB*PH*PL*PDH];
__device__ float g_K[PB*PH*PL*PDH];
__device__ float g_V[PB*PH*PL*PDH];
__device__ float g_kv[PB*PH*PL*PL];
__device__ float g_pq[PB*PH*PL*PDH];
__device__ float g_pk[PB*PH*PL*PDH];
__device__ float g_Am[PB*PH*PL*PL];
__device__ float g_attn[PT*PD];
__device__ float g_o[PT*PD];
__device__ float g_mh[PH*PL];
__device__ float g_cs[PH*PDH];

// ---------------- helpers ----------------
__device__ __forceinline__ uint32_t f2tf(float x) {
    uint32_t r;
    asm("cvt.rna.tf32.f32 %0, %1;" : "=r"(r) : "f"(x));
    return r;
}
__device__ __forceinline__ uint4 f4tf(const float4 v) {
    uint4 r;
    r.x = f2tf(v.x); r.y = f2tf(v.y); r.z = f2tf(v.z); r.w = f2tf(v.w);
    return r;
}
__device__ __forceinline__ uint32_t f2bf2(float lo, float hi) {
    __nv_bfloat162 h = __float22bfloat162_rn(make_float2(lo, hi));
    return *(uint32_t*)&h;
}

// ================= bf16 tensor-core GEMM (big projections) =================
// C = A @ W^T. A:[M,K] f32 row-major, W:[N,K] f32 row-major. M=N=K=2048.
// BM=BN=128, BK=32 (16 bf16x2 pairs), 256 threads (8 warps), warp tile 64x32
// via mma.sync.m16n8k16.bf16, double-buffered smem.
// EPI 0: permute (M,N)->(B,H,L,Dh).  EPI 4: bias add, row-major.
#define PSTR 20   // smem row stride in uint32 (16 pairs used + 4 pad)

template<int EPI>
__global__ __launch_bounds__(256, 2)
void bf_gemm(const float* __restrict__ Ag, const float* __restrict__ Wg,
             float* __restrict__ Cg, const float* __restrict__ bias)
{
    __shared__ uint32_t As[2][128*PSTR];
    __shared__ uint32_t Bs[2][128*PSTR];

    const int tid = threadIdx.x;
    const int lane = tid & 31;
    const int warpId = tid >> 5;
    const int g = lane >> 2;
    const int t = lane & 3;
    const int warpM = warpId >> 2;   // 0..1
    const int warpN = warpId & 3;    // 0..3
    const int m0 = blockIdx.y * 128;
    const int n0 = blockIdx.x * 128;

    // staging map: each thread loads 4 float4 per operand per stage
    const int row = tid >> 1;                 // 0..127
    const int fcb = (tid & 1) * 16;           // float col base: 0 or 16
    const int pib = (tid & 1) * 8;            // pair index base: 0 or 8

    float acc[4][4][4];
#pragma unroll
    for (int mt = 0; mt < 4; mt++)
#pragma unroll
        for (int nt = 0; nt < 4; nt++)
#pragma unroll
            for (int i = 0; i < 4; i++) acc[mt][nt][i] = 0.f;

    uint2 stA[4], stB[4];

    // prologue: stage 0 -> buffer 0
#pragma unroll
    for (int i = 0; i < 4; i++) {
        const float4 av = *(const float4*)(Ag + (long)(m0 + row) * PD + fcb + i*4);
        const float4 bv = *(const float4*)(Wg + (long)(n0 + row) * PD + fcb + i*4);
        stA[i] = make_uint2(f2bf2(av.x, av.y), f2bf2(av.z, av.w));
        stB[i] = make_uint2(f2bf2(bv.x, bv.y), f2bf2(bv.z, bv.w));
    }
#pragma unroll
    for (int i = 0; i < 4; i++) {
        *(uint2*)&As[0][row*PSTR + pib + i*2] = stA[i];
        *(uint2*)&Bs[0][row*PSTR + pib + i*2] = stB[i];
    }
    __syncthreads();

    const int NSTAGE = PD / 32;  // 64
    for (int s = 0; s < NSTAGE; s++) {
        const int buf = s & 1;
        const bool has = (s + 1) < NSTAGE;
        if (has) {
            const int kn = (s + 1) * 32;
#pragma unroll
            for (int i = 0; i < 4; i++) {
                const float4 av = *(const float4*)(Ag + (long)(m0 + row) * PD + kn + fcb + i*4);
                const float4 bv = *(const float4*)(Wg + (long)(n0 + row) * PD + kn + fcb + i*4);
                stA[i] = make_uint2(f2bf2(av.x, av.y), f2bf2(av.z, av.w));
                stB[i] = make_uint2(f2bf2(bv.x, bv.y), f2bf2(bv.z, bv.w));
            }
        }

        // compute on current buffer: kk in pair units {0, 8}
#pragma unroll
        for (int kk = 0; kk < 16; kk += 8) {
            uint32_t af[4][4];
#pragma unroll
            for (int mt = 0; mt < 4; mt++) {
                const int rb = (warpM*64 + mt*16 + g) * PSTR + kk + t;
                af[mt][0] = As[buf][rb];
                af[mt][1] = As[buf][rb + 8*PSTR];
                af[mt][2] = As[buf][rb + 4];
                af[mt][3] = As[buf][rb + 8*PSTR + 4];
            }
            uint32_t bfr[4][2];
#pragma unroll
            for (int nt = 0; nt < 4; nt++) {
                const int cb = (warpN*32 + nt*8 + g) * PSTR + kk + t;
                bfr[nt][0] = Bs[buf][cb];
                bfr[nt][1] = Bs[buf][cb + 4];
            }
#pragma unroll
            for (int mt = 0; mt < 4; mt++)
#pragma unroll
                for (int nt = 0; nt < 4; nt++) {
                    asm volatile(
                        "mma.sync.aligned.m16n8k16.row.col.f32.bf16.bf16.f32 "
                        "{%0,%1,%2,%3}, {%4,%5,%6,%7}, {%8,%9}, {%0,%1,%2,%3};\n"
                        : "+f"(acc[mt][nt][0]), "+f"(acc[mt][nt][1]),
                          "+f"(acc[mt][nt][2]), "+f"(acc[mt][nt][3])
                        : "r"(af[mt][0]), "r"(af[mt][1]), "r"(af[mt][2]), "r"(af[mt][3]),
                          "r"(bfr[nt][0]), "r"(bfr[nt][1]));
                }
        }

        if (has) {
            const int nb = buf ^ 1;
#pragma unroll
            for (int i = 0; i < 4; i++) {
                *(uint2*)&As[nb][row*PSTR + pib + i*2] = stA[i];
                *(uint2*)&Bs[nb][row*PSTR + pib + i*2] = stB[i];
            }
        }
        __syncthreads();
    }

    // epilogue
#pragma unroll
    for (int mt = 0; mt < 4; mt++) {
        const int rL = m0 + warpM*64 + mt*16 + g;
        const int rH = rL + 8;
#pragma unroll
        for (int nt = 0; nt < 4; nt++) {
            const int c = n0 + warpN*32 + nt*8 + t*2;
            float2 vL = make_float2(acc[mt][nt][0], acc[mt][nt][1]);
            float2 vH = make_float2(acc[mt][nt][2], acc[mt][nt][3]);
            if (EPI == 0) {
                const int h = c >> 8, d = c & 255;
                {
                    const int b = rL >> 8, l = rL & 255;
                    *(float2*)&Cg[(((long)(b*PH + h))*PL + l)*PDH + d] = vL;
                }
                {
                    const int b = rH >> 8, l = rH & 255;
                    *(float2*)&Cg[(((long)(b*PH + h))*PL + l)*PDH + d] = vH;
                }
            } else { // EPI == 4
                float2 bv = *(const float2*)&bias[c];
                *(float2*)&Cg[(long)rL*PD + c] = make_float2(vL.x + bv.x, vL.y + bv.y);
                *(float2*)&Cg[(long)rH*PD + c] = make_float2(vH.x + bv.x, vH.y + bv.y);
            }
        }
    }
}

// ================= tf32 mma GEMM (small batched GEMMs) =================
#define BK 16
#define ASTR 20
#define BSTR_NN 136

// EPI: 1 = plain batched row-major; 2 = causal-masked batched;
//      3 = attn-out (divide by rowsum(A), scatter to (B,L,D)).
template<int EPI, bool TRANSB>
__global__ __launch_bounds__(256)
void mma_gemm(const float* __restrict__ Ag, const float* __restrict__ Bg,
              float* __restrict__ Cg,
              int N, int Kd, int lda, int ldb,
              long strideA, long strideB, long strideC)
{
    constexpr int BSZ = TRANSB ? 128*ASTR : BK*BSTR_NN;
    __shared__ uint32_t As[2][128*ASTR];
    __shared__ uint32_t Bs[2][BSZ];

    const int tid = threadIdx.x;
    const int lane = tid & 31;
    const int warpId = tid >> 5;
    const int g = lane >> 2;
    const int t = lane & 3;
    const int warpM = warpId >> 2;
    const int warpN = warpId & 3;
    const int m0 = blockIdx.y * 128;
    const int n0 = blockIdx.x * 128;
    const int z  = blockIdx.z;
    const float* A  = Ag + (long)z * strideA;
    const float* Bm = Bg + (long)z * strideB;

    const int aRow = tid >> 2;
    const int aC4  = (tid & 3) * 4;
    const int bRowNN = tid >> 5;
    const int bC4NN  = (tid & 31) * 4;

    float acc[4][4][4];
#pragma unroll
    for (int mt = 0; mt < 4; mt++)
#pragma unroll
        for (int nt = 0; nt < 4; nt++)
#pragma unroll
            for (int i = 0; i < 4; i++) acc[mt][nt][i] = 0.f;

    float denL[4] = {0.f,0.f,0.f,0.f};
    float denH[4] = {0.f,0.f,0.f,0.f};

    uint4 ra0, ra1, rb0, rb1;
    {
        ra0 = f4tf(*(const float4*)(A + (long)(m0 + aRow)      * lda + aC4));
        ra1 = f4tf(*(const float4*)(A + (long)(m0 + aRow + 64) * lda + aC4));
        if (TRANSB) {
            rb0 = f4tf(*(const float4*)(Bm + (long)(n0 + aRow)      * ldb + aC4));
            rb1 = f4tf(*(const float4*)(Bm + (long)(n0 + aRow + 64) * ldb + aC4));
        } else {
            rb0 = f4tf(*(const float4*)(Bm + (long)(bRowNN)     * ldb + n0 + bC4NN));
            rb1 = f4tf(*(const float4*)(Bm + (long)(bRowNN + 8) * ldb + n0 + bC4NN));
        }
        *(uint4*)&As[0][aRow*ASTR + aC4]        = ra0;
        *(uint4*)&As[0][(aRow+64)*ASTR + aC4]   = ra1;
        if (TRANSB) {
            *(uint4*)&Bs[0][aRow*ASTR + aC4]      = rb0;
            *(uint4*)&Bs[0][(aRow+64)*ASTR + aC4] = rb1;
        } else {
            *(uint4*)&Bs[0][bRowNN*BSTR_NN + bC4NN]     = rb0;
            *(uint4*)&Bs[0][(bRowNN+8)*BSTR_NN + bC4NN] = rb1;
        }
    }
    __syncthreads();

    int buf = 0;
    for (int k0 = 0; k0 < Kd; k0 += BK) {
        const bool has = (k0 + BK) < Kd;
        if (has) {
            const int kn = k0 + BK;
            ra0 = f4tf(*(const float4*)(A + (long)(m0 + aRow)      * lda + kn + aC4));
            ra1 = f4tf(*(const float4*)(A + (long)(m0 + aRow + 64) * lda + kn + aC4));
            if (TRANSB) {
                rb0 = f4tf(*(const float4*)(Bm + (long)(n0 + aRow)      * ldb + kn + aC4));
                rb1 = f4tf(*(const float4*)(Bm + (long)(n0 + aRow + 64) * ldb + kn + aC4));
            } else {
                rb0 = f4tf(*(const float4*)(Bm + (long)(kn + bRowNN)     * ldb + n0 + bC4NN));
                rb1 = f4tf(*(const float4*)(Bm + (long)(kn + bRowNN + 8) * ldb + n0 + bC4NN));
            }
        }
#pragma unroll
        for (int kk = 0; kk < BK; kk += 8) {
            uint32_t af[4][4];
#pragma unroll
            for (int mt = 0; mt < 4; mt++) {
                const int rb = (warpM*64 + mt*16 + g) * ASTR + kk + t;
                af[mt][0] = As[buf][rb];
                af[mt][1] = As[buf][rb + 8*ASTR];
                af[mt][2] = As[buf][rb + 4];
                af[mt][3] = As[buf][rb + 8*ASTR + 4];
            }
            uint32_t bfr[4][2];
#pragma unroll
            for (int nt = 0; nt < 4; nt++) {
                const int cb = warpN*32 + nt*8 + g;
                if (TRANSB) {
                    bfr[nt][0] = Bs[buf][cb*ASTR + kk + t];
                    bfr[nt][1] = Bs[buf][cb*ASTR + kk + t + 4];
                } else {
                    bfr[nt][0] = Bs[buf][(kk + t)*BSTR_NN + cb];
                    bfr[nt][1] = Bs[buf][(kk + t + 4)*BSTR_NN + cb];
                }
            }
            if (EPI == 3) {
#pragma unroll
                for (int mt = 0; mt < 4; mt++) {
                    denL[mt] += __uint_as_float(af[mt][0]) + __uint_as_float(af[mt][2]);
                    denH[mt] += __uint_as_float(af[mt][1]) + __uint_as_float(af[mt][3]);
                }
            }
#pragma unroll
            for (int mt = 0; mt < 4; mt++)
#pragma unroll
                for (int nt = 0; nt < 4; nt++) {
                    asm volatile(
                        "mma.sync.aligned.m16n8k8.row.col.f32.tf32.tf32.f32 "
                        "{%0,%1,%2,%3}, {%4,%5,%6,%7}, {%8,%9}, {%0,%1,%2,%3};\n"
                        : "+f"(acc[mt][nt][0]), "+f"(acc[mt][nt][1]),
                          "+f"(acc[mt][nt][2]), "+f"(acc[mt][nt][3])
                        : "r"(af[mt][0]), "r"(af[mt][1]), "r"(af[mt][2]), "r"(af[mt][3]),
                          "r"(bfr[nt][0]), "r"(bfr[nt][1]));
                }
        }
        if (has) {
            const int nb = buf ^ 1;
            *(uint4*)&As[nb][aRow*ASTR + aC4]        = ra0;
            *(uint4*)&As[nb][(aRow+64)*ASTR + aC4]   = ra1;
            if (TRANSB) {
                *(uint4*)&Bs[nb][aRow*ASTR + aC4]      = rb0;
                *(uint4*)&Bs[nb][(aRow+64)*ASTR + aC4] = rb1;
            } else {
                *(uint4*)&Bs[nb][bRowNN*BSTR_NN + bC4NN]     = rb0;
                *(uint4*)&Bs[nb][(bRowNN+8)*BSTR_NN + bC4NN] = rb1;
            }
        }
        __syncthreads();
        buf ^= 1;
    }

    float invL[4], invH[4];
    if (EPI == 3) {
#pragma unroll
        for (int mt = 0; mt < 4; mt++) {
            float dl = denL[mt], dh = denH[mt];
            dl += __shfl_xor_sync(0xffffffffu, dl, 1);
            dl += __shfl_xor_sync(0xffffffffu, dl, 2);
            dh += __shfl_xor_sync(0xffffffffu, dh, 1);
            dh += __shfl_xor_sync(0xffffffffu, dh, 2);
            invL[mt] = 1.0f / fmaxf(dl, 1e-8f);
            invH[mt] = 1.0f / fmaxf(dh, 1e-8f);
        }
    }

#pragma unroll
    for (int mt = 0; mt < 4; mt++) {
        const int rL = m0 + warpM*64 + mt*16 + g;
        const int rH = rL + 8;
#pragma unroll
        for (int nt = 0; nt < 4; nt++) {
            const int c = n0 + warpN*32 + nt*8 + t*2;
            float2 vL = make_float2(acc[mt][nt][0], acc[mt][nt][1]);
            float2 vH = make_float2(acc[mt][nt][2], acc[mt][nt][3]);
            if (EPI == 1) {
                float* cz = Cg + (long)z * strideC;
                *(float2*)&cz[(long)rL*N + c] = vL;
                *(float2*)&cz[(long)rH*N + c] = vH;
            } else if (EPI == 2) {
                float* cz = Cg + (long)z * strideC;
                float2 wL = make_float2(c   <= rL ? vL.x : 0.f,
                                        c+1 <= rL ? vL.y : 0.f);
                float2 wH = make_float2(c   <= rH ? vH.x : 0.f,
                                        c+1 <= rH ? vH.y : 0.f);
                *(float2*)&cz[(long)rL*N + c] = wL;
                *(float2*)&cz[(long)rH*N + c] = wH;
            } else { // EPI == 3
                const int b = z / PH, h = z % PH;
                float2 wL = make_float2(vL.x*invL[mt], vL.y*invL[mt]);
                float2 wH = make_float2(vH.x*invH[mt], vH.y*invH[mt]);
                *(float2*)&Cg[((long)(b*PL + rL))*PD + h*PDH + c] = wL;
                *(float2*)&Cg[((long)(b*PL + rH))*PD + h*PDH + c] = wH;
            }
        }
    }
}

// ---------------- small kernels ----------------
__global__ void zero_mh_kernel(float* mh) {
    int i = blockIdx.x * blockDim.x + threadIdx.x;
    if (i < PH*PL) mh[i] = 0.f;
}

__global__ void mh_kernel(const float* __restrict__ kv, float* __restrict__ mh) {
    const int h = blockIdx.x, b = blockIdx.y, m = threadIdx.x;
    const float* base = kv + ((long)(b*PH + h) * PL) * PL + m;
    float s = 0.f;
#pragma unroll 4
    for (int l = 0; l < PL; l++) s += base[(long)l * PL];
    atomicAdd(&mh[h*PL + m], s * (1.0f / (float)(PB*PL)));
}

__global__ void cs_kernel(const float* __restrict__ mh, float* __restrict__ cs,
                          const float* __restrict__ alpha_p, const float* __restrict__ beta_p) {
    const int d = threadIdx.x;
    const float a = *alpha_p, bt = *beta_p;
    float c = 0.f;
    for (int h = 0; h < PH; h++) {
        cs[h*PDH + d] = c;
        c = bt * c + a * mh[h*PL + d];
    }
}

__global__ void phi_kernel(const float* __restrict__ Q, const float* __restrict__ K,
                           const float* __restrict__ kv, const float* __restrict__ cs,
                           float* __restrict__ pq, float* __restrict__ pk,
                           const float* __restrict__ alpha_p) {
    const long idx = (long)blockIdx.x * blockDim.x + threadIdx.x;
    const float a = *alpha_p;
    const int h = (int)((idx >> 16) & 7);
    const int d = (int)(idx & 255);
    const float c = cs[h*PDH + d];
    const float qm = Q[idx] * (c + a * (kv[idx] - c));
    pq[idx] = qm > 0.f ? qm + 1.f : __expf(qm);
    const float kk = K[idx];
    pk[idx] = kk > 0.f ? kk + 1.f : __expf(kk);
}

__global__ void ln_kernel(const float* __restrict__ q, const float* __restrict__ o,
                          const float* __restrict__ g, const float* __restrict__ be,
                          float* __restrict__ out) {
    const int tk = blockIdx.x;
    const int tid = threadIdx.x;
    __shared__ float red[256];
    const float* xq = q + (long)tk * PD;
    const float* xo = o + (long)tk * PD;
    float x[8];
    float s = 0.f;
#pragma unroll
    for (int i = 0; i < 8; i++) {
        x[i] = xq[tid + i*256] + xo[tid + i*256];
        s += x[i];
    }
    red[tid] = s; __syncthreads();
    for (int st = 128; st > 0; st >>= 1) {
        if (tid < st) red[tid] += red[tid + st];
        __syncthreads();
    }
    const float mu = red[0] * (1.0f / PD);
    __syncthreads();
    float v = 0.f;
#pragma unroll
    for (int i = 0; i < 8; i++) { const float dd = x[i] - mu; v += dd*dd; }
    red[tid] = v; __syncthreads();
    for (int st = 128; st > 0; st >>= 1) {
        if (tid < st) red[tid] += red[tid + st];
        __syncthreads();
    }
    const float inv = rsqrtf(red[0] * (1.0f / PD) + 1e-5f);
#pragma unroll
    for (int i = 0; i < 8; i++) {
        const int c = tid + i*256;
        out[(long)tk*PD + c] = (x[i] - mu) * inv * g[c] + be[c];
    }
}

// ---------------- launch ----------------
extern "C" void kernel_launch(void* const* d_in, const int* in_sizes, int n_in,
                              void* d_out, int out_size) {
    const float* query = (const float*)d_in[0];
    const float* key   = (const float*)d_in[1];
    const float* value = (const float*)d_in[2];
    const float* Wq    = (const float*)d_in[3];
    const float* Wk    = (const float*)d_in[4];
    const float* Wv    = (const float*)d_in[5];
    const float* Wo    = (const float*)d_in[6];
    const float* bo    = (const float*)d_in[7];
    const float* ln_g  = (const float*)d_in[8];
    const float* ln_b  = (const float*)d_in[9];
    const float* alpha = (const float*)d_in[10];
    const float* beta  = (const float*)d_in[11];
    float* out = (float*)d_out;

    float *Q, *K, *V, *kv, *pq, *pk, *Am, *attn, *o, *mh, *cs;
    cudaGetSymbolAddress((void**)&Q,  g_Q);
    cudaGetSymbolAddress((void**)&K,  g_K);
    cudaGetSymbolAddress((void**)&V,  g_V);
    cudaGetSymbolAddress((void**)&kv, g_kv);
    cudaGetSymbolAddress((void**)&pq, g_pq);
    cudaGetSymbolAddress((void**)&pk, g_pk);
    cudaGetSymbolAddress((void**)&Am, g_Am);
    cudaGetSymbolAddress((void**)&attn, g_attn);
    cudaGetSymbolAddress((void**)&o,  g_o);
    cudaGetSymbolAddress((void**)&mh, g_mh);
    cudaGetSymbolAddress((void**)&cs, g_cs);

    dim3 blk(256);
    dim3 gProj(PD/128, PT/128, 1);          // 16 x 16
    dim3 gBat(PL/128, PL/128, PB*PH);       // 2 x 2 x 64

    // 1. projections (X @ W^T) with permute epilogue to (B,H,L,Dh) — bf16 MMA
    bf_gemm<0><<<gProj, blk>>>(query, Wq, Q, nullptr);
    bf_gemm<0><<<gProj, blk>>>(key,   Wk, K, nullptr);
    bf_gemm<0><<<gProj, blk>>>(value, Wv, V, nullptr);

    // 2. kv = K @ V^T per (b,h) — tf32
    mma_gemm<1,true><<<gBat, blk>>>(K, V, kv, PL, PDH, PDH, PDH,
                                    (long)PL*PDH, (long)PL*PDH, (long)PL*PL);

    // 3. mh = mean over (b,l) of kv
    zero_mh_kernel<<<(PH*PL + 255)/256, 256>>>(mh);
    mh_kernel<<<dim3(PH, PB), 256>>>(kv, mh);

    // 4. cs scan over heads
    cs_kernel<<<1, 256>>>(mh, cs, alpha, beta);

    // 5. pq/pk elementwise
    phi_kernel<<<(PB*PH*PL*PDH)/1024, 1024>>>(Q, K, kv, cs, pq, pk, alpha);

    // 6. A = tril(pq @ pk^T) per (b,h) — tf32
    mma_gemm<2,true><<<gBat, blk>>>(pq, pk, Am, PL, PDH, PDH, PDH,
                                    (long)PL*PDH, (long)PL*PDH, (long)PL*PL);

    // 7. attn = (A @ V) / rowsum(A), scattered to (B,L,D) — tf32
    mma_gemm<3,false><<<gBat, blk>>>(Am, V, attn, PDH, PL, PL, PDH,
                                     (long)PL*PL, (long)PL*PDH, 0);

    // 8. o = attn @ Wo^T + bo — bf16 MMA
    bf_gemm<4><<<gProj, blk>>>(attn, Wo, o, bo);

    // 9. residual + layernorm
    ln_kernel<<<PT, 256>>>(query, o, ln_g, ln_b, out);
}

// round 5
// speedup vs baseline: 5.4846x; 1.6324x over previous
#include <cuda_runtime.h>
#include <cuda_bf16.h>
#include <math.h>
#include <stdint.h>

// Problem constants
#define PB 8       // batch
#define PL 256     // seq len
#define PD 2048    // d_model
#define PH 8       // heads
#define PDH 256    // head dim
#define PT (PB*PL) // tokens = 2048

// ---------------- scratch ----------------
__device__ float g_Q[PB*PH*PL*PDH];
__device__ float g_K[PB*PH*PL*PDH];
__device__ float g_V[PB*PH*PL*PDH];
__device__ float g_kv[PB*PH*PL*PL];
__device__ float g_pq[PB*PH*PL*PDH];
__device__ float g_pk[PB*PH*PL*PDH];
__device__ float g_Am[PB*PH*PL*PL];
__device__ float g_o[PT*PD];
__device__ float g_mh[PH*PL];
__device__ float g_cs[PH*PDH];

// bf16 copies of GEMM operands
__device__ __nv_bfloat16 g_qbf[PT*PD];
__device__ __nv_bfloat16 g_kbf[PT*PD];
__device__ __nv_bfloat16 g_vbf[PT*PD];
__device__ __nv_bfloat16 g_wqbf[PD*PD];
__device__ __nv_bfloat16 g_wkbf[PD*PD];
__device__ __nv_bfloat16 g_wvbf[PD*PD];
__device__ __nv_bfloat16 g_wobf[PD*PD];
__device__ __nv_bfloat16 g_attnbf[PT*PD];

// ---------------- helpers ----------------
__device__ __forceinline__ uint32_t f2tf(float x) {
    uint32_t r;
    asm("cvt.rna.tf32.f32 %0, %1;" : "=r"(r) : "f"(x));
    return r;
}
__device__ __forceinline__ uint4 f4tf(const float4 v) {
    uint4 r;
    r.x = f2tf(v.x); r.y = f2tf(v.y); r.z = f2tf(v.z); r.w = f2tf(v.w);
    return r;
}
__device__ __forceinline__ uint32_t f2bf2(float lo, float hi) {
    __nv_bfloat162 h = __float22bfloat162_rn(make_float2(lo, hi));
    return *(uint32_t*)&h;
}
__device__ __forceinline__ uint32_t smem_u32(const void* p) {
    uint32_t a;
    asm("{ .reg .u64 t; cvta.to.shared.u64 t, %1; cvt.u32.u64 %0, t; }" : "=r"(a) : "l"(p));
    return a;
}

#define CP_ASYNC16(dst, src) \
    asm volatile("cp.async.cg.shared.global [%0], [%1], 16;" :: "r"(dst), "l"(src))
#define CP_COMMIT() asm volatile("cp.async.commit_group;")
#define LDSM4(r0, r1, r2, r3, a) \
    asm volatile("ldmatrix.sync.aligned.m8n8.x4.shared.b16 {%0,%1,%2,%3}, [%4];" \
        : "=r"(r0), "=r"(r1), "=r"(r2), "=r"(r3) : "r"(a))

// ================= convert fp32 -> bf16 (4 floats/thread) =================
__global__ void cvt_kernel(const float* __restrict__ src, __nv_bfloat16* __restrict__ dst) {
    const long i4 = (long)blockIdx.x * blockDim.x + threadIdx.x;
    const float4 v = *(const float4*)(src + i4 * 4);
    uint2 p = make_uint2(f2bf2(v.x, v.y), f2bf2(v.z, v.w));
    *(uint2*)(dst + i4 * 4) = p;
}

// ================= bf16 pipelined tensor-core GEMM =================
// C = A @ W^T. A:[2048,2048] bf16 row-major, W:[2048,2048] bf16 row-major.
// BM=BN=128, BK=32, 256 thr (8 warps), warp tile 64x32, m16n8k16.
// 4-stage cp.async pipeline, ldmatrix fragment loads.
// EPI 0: permute (M,N)->(B,H,L,Dh).  EPI 4: bias add, row-major fp32.
#define PSTR 20                 // smem row stride in words
#define STG_WORDS (128*PSTR)    // 2560 words per operand tile
#define NST 4                   // pipeline stages
#define BF_SMEM_BYTES (2*NST*STG_WORDS*4)   // 81920

template<int EPI>
__global__ __launch_bounds__(256, 2)
void bf_gemm(const __nv_bfloat16* __restrict__ Ag, const __nv_bfloat16* __restrict__ Wg,
             float* __restrict__ Cg, const float* __restrict__ bias)
{
    extern __shared__ __align__(16) uint32_t sm[];
    const uint32_t sbase = smem_u32(sm);

    const int tid = threadIdx.x;
    const int lane = tid & 31;
    const int warpId = tid >> 5;
    const int g = lane >> 2;
    const int t = lane & 3;
    const int warpM = warpId >> 2;   // 0..1
    const int warpN = warpId & 3;    // 0..3
    const int m0 = blockIdx.y * 128;
    const int n0 = blockIdx.x * 128;

    // cp.async per-thread map: 2 granules (16B) per operand per stage
    const int gid0 = tid, gid1 = tid + 256;
    const int row0 = gid0 >> 2, gc0 = gid0 & 3;
    const int row1 = gid1 >> 2, gc1 = gid1 & 3;
    const uint32_t d0 = (row0 * PSTR + gc0 * 4) * 4;  // byte offset inside tile
    const uint32_t d1 = (row1 * PSTR + gc1 * 4) * 4;

    // ldmatrix per-thread byte offsets (inside a tile), kk added later
    uint32_t aoff[4];
#pragma unroll
    for (int mt = 0; mt < 4; mt++) {
        const int ar = warpM * 64 + mt * 16 + (lane & 15);
        const int ac = (lane >> 4) * 4;
        aoff[mt] = (ar * PSTR + ac) * 4;
    }
    uint32_t boff[2];
#pragma unroll
    for (int p = 0; p < 2; p++) {
        const int br = warpN * 32 + p * 16 + (lane & 7) + ((lane >> 4) << 3);
        const int bc = ((lane >> 3) & 1) * 4;
        boff[p] = (br * PSTR + bc) * 4;
    }

    float acc[4][4][4];
#pragma unroll
    for (int mt = 0; mt < 4; mt++)
#pragma unroll
        for (int nt = 0; nt < 4; nt++)
#pragma unroll
            for (int i = 0; i < 4; i++) acc[mt][nt][i] = 0.f;

    auto issue = [&](int s) {
        const int st = s & (NST - 1);
        const uint32_t aT = sbase + st * STG_WORDS * 4;
        const uint32_t bT = sbase + (NST + st) * STG_WORDS * 4;
        const int k0 = s * 32;
        CP_ASYNC16(aT + d0, Ag + (long)(m0 + row0) * PD + k0 + gc0 * 8);
        CP_ASYNC16(aT + d1, Ag + (long)(m0 + row1) * PD + k0 + gc1 * 8);
        CP_ASYNC16(bT + d0, Wg + (long)(n0 + row0) * PD + k0 + gc0 * 8);
        CP_ASYNC16(bT + d1, Wg + (long)(n0 + row1) * PD + k0 + gc1 * 8);
        CP_COMMIT();
    };

    const int NSTAGE = PD / 32;  // 64
    issue(0);
    issue(1);

    for (int s = 0; s < NSTAGE; s++) {
        if (s + 2 < NSTAGE) {
            issue(s + 2);
            asm volatile("cp.async.wait_group 2;");
        } else if (s + 1 < NSTAGE) {
            asm volatile("cp.async.wait_group 1;");
        } else {
            asm volatile("cp.async.wait_group 0;");
        }
        __syncthreads();

        const int st = s & (NST - 1);
        const uint32_t aT = sbase + st * STG_WORDS * 4;
        const uint32_t bT = sbase + (NST + st) * STG_WORDS * 4;

#pragma unroll
        for (int kk = 0; kk < 16; kk += 8) {
            uint32_t af[4][4];
#pragma unroll
            for (int mt = 0; mt < 4; mt++)
                LDSM4(af[mt][0], af[mt][1], af[mt][2], af[mt][3], aT + aoff[mt] + kk * 4);
            uint32_t bfr[4][2];
#pragma unroll
            for (int p = 0; p < 2; p++)
                LDSM4(bfr[2*p][0], bfr[2*p][1], bfr[2*p+1][0], bfr[2*p+1][1],
                      bT + boff[p] + kk * 4);
#pragma unroll
            for (int mt = 0; mt < 4; mt++)
#pragma unroll
                for (int nt = 0; nt < 4; nt++) {
                    asm volatile(
                        "mma.sync.aligned.m16n8k16.row.col.f32.bf16.bf16.f32 "
                        "{%0,%1,%2,%3}, {%4,%5,%6,%7}, {%8,%9}, {%0,%1,%2,%3};\n"
                        : "+f"(acc[mt][nt][0]), "+f"(acc[mt][nt][1]),
                          "+f"(acc[mt][nt][2]), "+f"(acc[mt][nt][3])
                        : "r"(af[mt][0]), "r"(af[mt][1]), "r"(af[mt][2]), "r"(af[mt][3]),
                          "r"(bfr[nt][0]), "r"(bfr[nt][1]));
                }
        }
    }

    // epilogue
#pragma unroll
    for (int mt = 0; mt < 4; mt++) {
        const int rL = m0 + warpM*64 + mt*16 + g;
        const int rH = rL + 8;
#pragma unroll
        for (int nt = 0; nt < 4; nt++) {
            const int c = n0 + warpN*32 + nt*8 + t*2;
            float2 vL = make_float2(acc[mt][nt][0], acc[mt][nt][1]);
            float2 vH = make_float2(acc[mt][nt][2], acc[mt][nt][3]);
            if (EPI == 0) {
                const int h = c >> 8, d = c & 255;
                {
                    const int b = rL >> 8, l = rL & 255;
                    *(float2*)&Cg[(((long)(b*PH + h))*PL + l)*PDH + d] = vL;
                }
                {
                    const int b = rH >> 8, l = rH & 255;
                    *(float2*)&Cg[(((long)(b*PH + h))*PL + l)*PDH + d] = vH;
                }
            } else { // EPI == 4
                float2 bv = *(const float2*)&bias[c];
                *(float2*)&Cg[(long)rL*PD + c] = make_float2(vL.x + bv.x, vL.y + bv.y);
                *(float2*)&Cg[(long)rH*PD + c] = make_float2(vH.x + bv.x, vH.y + bv.y);
            }
        }
    }
}

// ================= tf32 mma GEMM (small batched GEMMs) =================
#define BK 16
#define ASTR 20
#define BSTR_NN 136

// EPI: 1 = plain batched row-major; 2 = causal-masked batched;
//      3 = attn-out (divide by rowsum(A), scatter bf16 to (B,L,D)).
template<int EPI, bool TRANSB>
__global__ __launch_bounds__(256)
void mma_gemm(const float* __restrict__ Ag, const float* __restrict__ Bg,
              float* __restrict__ Cg,
              int N, int Kd, int lda, int ldb,
              long strideA, long strideB, long strideC)
{
    constexpr int BSZ = TRANSB ? 128*ASTR : BK*BSTR_NN;
    __shared__ uint32_t As[2][128*ASTR];
    __shared__ uint32_t Bs[2][BSZ];

    const int tid = threadIdx.x;
    const int lane = tid & 31;
    const int warpId = tid >> 5;
    const int g = lane >> 2;
    const int t = lane & 3;
    const int warpM = warpId >> 2;
    const int warpN = warpId & 3;
    const int m0 = blockIdx.y * 128;
    const int n0 = blockIdx.x * 128;
    const int z  = blockIdx.z;
    const float* A  = Ag + (long)z * strideA;
    const float* Bm = Bg + (long)z * strideB;

    const int aRow = tid >> 2;
    const int aC4  = (tid & 3) * 4;
    const int bRowNN = tid >> 5;
    const int bC4NN  = (tid & 31) * 4;

    float acc[4][4][4];
#pragma unroll
    for (int mt = 0; mt < 4; mt++)
#pragma unroll
        for (int nt = 0; nt < 4; nt++)
#pragma unroll
            for (int i = 0; i < 4; i++) acc[mt][nt][i] = 0.f;

    float denL[4] = {0.f,0.f,0.f,0.f};
    float denH[4] = {0.f,0.f,0.f,0.f};

    uint4 ra0, ra1, rb0, rb1;
    {
        ra0 = f4tf(*(const float4*)(A + (long)(m0 + aRow)      * lda + aC4));
        ra1 = f4tf(*(const float4*)(A + (long)(m0 + aRow + 64) * lda + aC4));
        if (TRANSB) {
            rb0 = f4tf(*(const float4*)(Bm + (long)(n0 + aRow)      * ldb + aC4));
            rb1 = f4tf(*(const float4*)(Bm + (long)(n0 + aRow + 64) * ldb + aC4));
        } else {
            rb0 = f4tf(*(const float4*)(Bm + (long)(bRowNN)     * ldb + n0 + bC4NN));
            rb1 = f4tf(*(const float4*)(Bm + (long)(bRowNN + 8) * ldb + n0 + bC4NN));
        }
        *(uint4*)&As[0][aRow*ASTR + aC4]        = ra0;
        *(uint4*)&As[0][(aRow+64)*ASTR + aC4]   = ra1;
        if (TRANSB) {
            *(uint4*)&Bs[0][aRow*ASTR + aC4]      = rb0;
            *(uint4*)&Bs[0][(aRow+64)*ASTR + aC4] = rb1;
        } else {
            *(uint4*)&Bs[0][bRowNN*BSTR_NN + bC4NN]     = rb0;
            *(uint4*)&Bs[0][(bRowNN+8)*BSTR_NN + bC4NN] = rb1;
        }
    }
    __syncthreads();

    int buf = 0;
    for (int k0 = 0; k0 < Kd; k0 += BK) {
        const bool has = (k0 + BK) < Kd;
        if (has) {
            const int kn = k0 + BK;
            ra0 = f4tf(*(const float4*)(A + (long)(m0 + aRow)      * lda + kn + aC4));
            ra1 = f4tf(*(const float4*)(A + (long)(m0 + aRow + 64) * lda + kn + aC4));
            if (TRANSB) {
                rb0 = f4tf(*(const float4*)(Bm + (long)(n0 + aRow)      * ldb + kn + aC4));
                rb1 = f4tf(*(const float4*)(Bm + (long)(n0 + aRow + 64) * ldb + kn + aC4));
            } else {
                rb0 = f4tf(*(const float4*)(Bm + (long)(kn + bRowNN)     * ldb + n0 + bC4NN));
                rb1 = f4tf(*(const float4*)(Bm + (long)(kn + bRowNN + 8) * ldb + n0 + bC4NN));
            }
        }
#pragma unroll
        for (int kk = 0; kk < BK; kk += 8) {
            uint32_t af[4][4];
#pragma unroll
            for (int mt = 0; mt < 4; mt++) {
                const int rb = (warpM*64 + mt*16 + g) * ASTR + kk + t;
                af[mt][0] = As[buf][rb];
                af[mt][1] = As[buf][rb + 8*ASTR];
                af[mt][2] = As[buf][rb + 4];
                af[mt][3] = As[buf][rb + 8*ASTR + 4];
            }
            uint32_t bfr[4][2];
#pragma unroll
            for (int nt = 0; nt < 4; nt++) {
                const int cb = warpN*32 + nt*8 + g;
                if (TRANSB) {
                    bfr[nt][0] = Bs[buf][cb*ASTR + kk + t];
                    bfr[nt][1] = Bs[buf][cb*ASTR + kk + t + 4];
                } else {
                    bfr[nt][0] = Bs[buf][(kk + t)*BSTR_NN + cb];
                    bfr[nt][1] = Bs[buf][(kk + t + 4)*BSTR_NN + cb];
                }
            }
            if (EPI == 3) {
#pragma unroll
                for (int mt = 0; mt < 4; mt++) {
                    denL[mt] += __uint_as_float(af[mt][0]) + __uint_as_float(af[mt][2]);
                    denH[mt] += __uint_as_float(af[mt][1]) + __uint_as_float(af[mt][3]);
                }
            }
#pragma unroll
            for (int mt = 0; mt < 4; mt++)
#pragma unroll
                for (int nt = 0; nt < 4; nt++) {
                    asm volatile(
                        "mma.sync.aligned.m16n8k8.row.col.f32.tf32.tf32.f32 "
                        "{%0,%1,%2,%3}, {%4,%5,%6,%7}, {%8,%9}, {%0,%1,%2,%3};\n"
                        : "+f"(acc[mt][nt][0]), "+f"(acc[mt][nt][1]),
                          "+f"(acc[mt][nt][2]), "+f"(acc[mt][nt][3])
                        : "r"(af[mt][0]), "r"(af[mt][1]), "r"(af[mt][2]), "r"(af[mt][3]),
                          "r"(bfr[nt][0]), "r"(bfr[nt][1]));
                }
        }
        if (has) {
            const int nb = buf ^ 1;
            *(uint4*)&As[nb][aRow*ASTR + aC4]        = ra0;
            *(uint4*)&As[nb][(aRow+64)*ASTR + aC4]   = ra1;
            if (TRANSB) {
                *(uint4*)&Bs[nb][aRow*ASTR + aC4]      = rb0;
                *(uint4*)&Bs[nb][(aRow+64)*ASTR + aC4] = rb1;
            } else {
                *(uint4*)&Bs[nb][bRowNN*BSTR_NN + bC4NN]     = rb0;
                *(uint4*)&Bs[nb][(bRowNN+8)*BSTR_NN + bC4NN] = rb1;
            }
        }
        __syncthreads();
        buf ^= 1;
    }

    float invL[4], invH[4];
    if (EPI == 3) {
#pragma unroll
        for (int mt = 0; mt < 4; mt++) {
            float dl = denL[mt], dh = denH[mt];
            dl += __shfl_xor_sync(0xffffffffu, dl, 1);
            dl += __shfl_xor_sync(0xffffffffu, dl, 2);
            dh += __shfl_xor_sync(0xffffffffu, dh, 1);
            dh += __shfl_xor_sync(0xffffffffu, dh, 2);
            invL[mt] = 1.0f / fmaxf(dl, 1e-8f);
            invH[mt] = 1.0f / fmaxf(dh, 1e-8f);
        }
    }

#pragma unroll
    for (int mt = 0; mt < 4; mt++) {
        const int rL = m0 + warpM*64 + mt*16 + g;
        const int rH = rL + 8;
#pragma unroll
        for (int nt = 0; nt < 4; nt++) {
            const int c = n0 + warpN*32 + nt*8 + t*2;
            float2 vL = make_float2(acc[mt][nt][0], acc[mt][nt][1]);
            float2 vH = make_float2(acc[mt][nt][2], acc[mt][nt][3]);
            if (EPI == 1) {
                float* cz = Cg + (long)z * strideC;
                *(float2*)&cz[(long)rL*N + c] = vL;
                *(float2*)&cz[(long)rH*N + c] = vH;
            } else if (EPI == 2) {
                float* cz = Cg + (long)z * strideC;
                float2 wL = make_float2(c   <= rL ? vL.x : 0.f,
                                        c+1 <= rL ? vL.y : 0.f);
                float2 wH = make_float2(c   <= rH ? vH.x : 0.f,
                                        c+1 <= rH ? vH.y : 0.f);
                *(float2*)&cz[(long)rL*N + c] = wL;
                *(float2*)&cz[(long)rH*N + c] = wH;
            } else { // EPI == 3: write bf16 into (B,L,D) buffer
                const int b = z / PH, h = z % PH;
                uint32_t* cb16 = (uint32_t*)Cg;
                const long iL = ((long)(b*PL + rL))*PD + h*PDH + c;
                const long iH = ((long)(b*PL + rH))*PD + h*PDH + c;
                cb16[iL >> 1] = f2bf2(vL.x*invL[mt], vL.y*invL[mt]);
                cb16[iH >> 1] = f2bf2(vH.x*invH[mt], vH.y*invH[mt]);
            }
        }
    }
}

// ---------------- small kernels ----------------
__global__ void zero_mh_kernel(float* mh) {
    int i = blockIdx.x * blockDim.x + threadIdx.x;
    if (i < PH*PL) mh[i] = 0.f;
}

__global__ void mh_kernel(const float* __restrict__ kv, float* __restrict__ mh) {
    const int h = blockIdx.x, b = blockIdx.y, m = threadIdx.x;
    const float* base = kv + ((long)(b*PH + h) * PL) * PL + m;
    float s = 0.f;
#pragma unroll 4
    for (int l = 0; l < PL; l++) s += base[(long)l * PL];
    atomicAdd(&mh[h*PL + m], s * (1.0f / (float)(PB*PL)));
}

__global__ void cs_kernel(const float* __restrict__ mh, float* __restrict__ cs,
                          const float* __restrict__ alpha_p, const float* __restrict__ beta_p) {
    const int d = threadIdx.x;
    const float a = *alpha_p, bt = *beta_p;
    float c = 0.f;
    for (int h = 0; h < PH; h++) {
        cs[h*PDH + d] = c;
        c = bt * c + a * mh[h*PL + d];
    }
}

__global__ void phi_kernel(const float* __restrict__ Q, const float* __restrict__ K,
                           const float* __restrict__ kv, const float* __restrict__ cs,
                           float* __restrict__ pq, float* __restrict__ pk,
                           const float* __restrict__ alpha_p) {
    const long idx = (long)blockIdx.x * blockDim.x + threadIdx.x;
    const float a = *alpha_p;
    const int h = (int)((idx >> 16) & 7);
    const int d = (int)(idx & 255);
    const float c = cs[h*PDH + d];
    const float qm = Q[idx] * (c + a * (kv[idx] - c));
    pq[idx] = qm > 0.f ? qm + 1.f : __expf(qm);
    const float kk = K[idx];
    pk[idx] = kk > 0.f ? kk + 1.f : __expf(kk);
}

__global__ void ln_kernel(const float* __restrict__ q, const float* __restrict__ o,
                          const float* __restrict__ g, const float* __restrict__ be,
                          float* __restrict__ out) {
    const int tk = blockIdx.x;
    const int tid = threadIdx.x;
    __shared__ float red[256];
    const float* xq = q + (long)tk * PD;
    const float* xo = o + (long)tk * PD;
    float x[8];
    float s = 0.f;
#pragma unroll
    for (int i = 0; i < 8; i++) {
        x[i] = xq[tid + i*256] + xo[tid + i*256];
        s += x[i];
    }
    red[tid] = s; __syncthreads();
    for (int st = 128; st > 0; st >>= 1) {
        if (tid < st) red[tid] += red[tid + st];
        __syncthreads();
    }
    const float mu = red[0] * (1.0f / PD);
    __syncthreads();
    float v = 0.f;
#pragma unroll
    for (int i = 0; i < 8; i++) { const float dd = x[i] - mu; v += dd*dd; }
    red[tid] = v; __syncthreads();
    for (int st = 128; st > 0; st >>= 1) {
        if (tid < st) red[tid] += red[tid + st];
        __syncthreads();
    }
    const float inv = rsqrtf(red[0] * (1.0f / PD) + 1e-5f);
#pragma unroll
    for (int i = 0; i < 8; i++) {
        const int c = tid + i*256;
        out[(long)tk*PD + c] = (x[i] - mu) * inv * g[c] + be[c];
    }
}

// ---------------- launch ----------------
extern "C" void kernel_launch(void* const* d_in, const int* in_sizes, int n_in,
                              void* d_out, int out_size) {
    const float* query = (const float*)d_in[0];
    const float* key   = (const float*)d_in[1];
    const float* value = (const float*)d_in[2];
    const float* Wq    = (const float*)d_in[3];
    const float* Wk    = (const float*)d_in[4];
    const float* Wv    = (const float*)d_in[5];
    const float* Wo    = (const float*)d_in[6];
    const float* bo    = (const float*)d_in[7];
    const float* ln_g  = (const float*)d_in[8];
    const float* ln_b  = (const float*)d_in[9];
    const float* alpha = (const float*)d_in[10];
    const float* beta  = (const float*)d_in[11];
    float* out = (float*)d_out;

    float *Q, *K, *V, *kv, *pq, *pk, *Am, *o, *mh, *cs;
    __nv_bfloat16 *qbf, *kbf, *vbf, *wqbf, *wkbf, *wvbf, *wobf, *attnbf;
    cudaGetSymbolAddress((void**)&Q,  g_Q);
    cudaGetSymbolAddress((void**)&K,  g_K);
    cudaGetSymbolAddress((void**)&V,  g_V);
    cudaGetSymbolAddress((void**)&kv, g_kv);
    cudaGetSymbolAddress((void**)&pq, g_pq);
    cudaGetSymbolAddress((void**)&pk, g_pk);
    cudaGetSymbolAddress((void**)&Am, g_Am);
    cudaGetSymbolAddress((void**)&o,  g_o);
    cudaGetSymbolAddress((void**)&mh, g_mh);
    cudaGetSymbolAddress((void**)&cs, g_cs);
    cudaGetSymbolAddress((void**)&qbf, g_qbf);
    cudaGetSymbolAddress((void**)&kbf, g_kbf);
    cudaGetSymbolAddress((void**)&vbf, g_vbf);
    cudaGetSymbolAddress((void**)&wqbf, g_wqbf);
    cudaGetSymbolAddress((void**)&wkbf, g_wkbf);
    cudaGetSymbolAddress((void**)&wvbf, g_wvbf);
    cudaGetSymbolAddress((void**)&wobf, g_wobf);
    cudaGetSymbolAddress((void**)&attnbf, g_attnbf);

    cudaFuncSetAttribute(bf_gemm<0>, cudaFuncAttributeMaxDynamicSharedMemorySize, BF_SMEM_BYTES);
    cudaFuncSetAttribute(bf_gemm<4>, cudaFuncAttributeMaxDynamicSharedMemorySize, BF_SMEM_BYTES);

    dim3 blk(256);
    dim3 gProj(PD/128, PT/128, 1);          // 16 x 16
    dim3 gBat(PL/128, PL/128, PB*PH);       // 2 x 2 x 64
    const int CVB = (PT*PD/4) / 256;        // 4096 blocks per 4M-element array

    // 0. convert inputs + weights to bf16
    cvt_kernel<<<CVB, 256>>>(query, qbf);
    cvt_kernel<<<CVB, 256>>>(key,   kbf);
    cvt_kernel<<<CVB, 256>>>(value, vbf);
    cvt_kernel<<<CVB, 256>>>(Wq, wqbf);
    cvt_kernel<<<CVB, 256>>>(Wk, wkbf);
    cvt_kernel<<<CVB, 256>>>(Wv, wvbf);
    cvt_kernel<<<CVB, 256>>>(Wo, wobf);

    // 1. projections (X @ W^T) with permute epilogue to (B,H,L,Dh)
    bf_gemm<0><<<gProj, blk, BF_SMEM_BYTES>>>(qbf, wqbf, Q, nullptr);
    bf_gemm<0><<<gProj, blk, BF_SMEM_BYTES>>>(kbf, wkbf, K, nullptr);
    bf_gemm<0><<<gProj, blk, BF_SMEM_BYTES>>>(vbf, wvbf, V, nullptr);

    // 2. kv = K @ V^T per (b,h) — tf32
    mma_gemm<1,true><<<gBat, blk>>>(K, V, kv, PL, PDH, PDH, PDH,
                                    (long)PL*PDH, (long)PL*PDH, (long)PL*PL);

    // 3. mh = mean over (b,l) of kv
    zero_mh_kernel<<<(PH*PL + 255)/256, 256>>>(mh);
    mh_kernel<<<dim3(PH, PB), 256>>>(kv, mh);

    // 4. cs scan over heads
    cs_kernel<<<1, 256>>>(mh, cs, alpha, beta);

    // 5. pq/pk elementwise
    phi_kernel<<<(PB*PH*PL*PDH)/1024, 1024>>>(Q, K, kv, cs, pq, pk, alpha);

    // 6. A = tril(pq @ pk^T) per (b,h) — tf32
    mma_gemm<2,true><<<gBat, blk>>>(pq, pk, Am, PL, PDH, PDH, PDH,
                                    (long)PL*PDH, (long)PL*PDH, (long)PL*PL);

    // 7. attn = (A @ V) / rowsum(A), scatter bf16 to (B,L,D) — tf32
    mma_gemm<3,false><<<gBat, blk>>>(Am, V, (float*)attnbf, PDH, PL, PL, PDH,
                                     (long)PL*PL, (long)PL*PDH, 0);

    // 8. o = attn @ Wo^T + bo — bf16 pipelined
    bf_gemm<4><<<gProj, blk, BF_SMEM_BYTES>>>(attnbf, wobf, o, bo);

    // 9. residual + layernorm
    ln_kernel<<<PT, 256>>>(query, o, ln_g, ln_b, out);
}

// round 6
// speedup vs baseline: 6.0837x; 1.1092x over previous
#include <cuda_runtime.h>
#include <cuda_bf16.h>
#include <math.h>
#include <stdint.h>

// Problem constants
#define PB 8
#define PL 256
#define PD 2048
#define PH 8
#define PDH 256
#define PT (PB*PL)
#define BH (PB*PH)

// ---------------- scratch ----------------
__device__ float g_Q[BH*PL*PDH];          // fp32 Q (B,H,L,Dh) for phi
__device__ float g_K[BH*PL*PDH];          // fp32 K for phi
__device__ float g_kv[BH*PL*PL];          // fp32 kv
__device__ float g_o[PT*PD];
__device__ float g_mh[PH*PL];
__device__ float g_cs[PH*PDH];

__device__ __nv_bfloat16 g_kbhl[BH*PL*PDH];   // K bf16 (B,H,L,Dh)
__device__ __nv_bfloat16 g_vbhl[BH*PL*PDH];   // V bf16 (B,H,L,Dh)
__device__ __nv_bfloat16 g_vt[BH*PDH*PL];     // V^T bf16 (B,H,Dh,L)
__device__ __nv_bfloat16 g_pq[BH*PL*PDH];
__device__ __nv_bfloat16 g_pk[BH*PL*PDH];
__device__ __nv_bfloat16 g_Am[BH*PL*PL];      // causal A bf16
__device__ __nv_bfloat16 g_attnbf[PT*PD];     // attn (B,L,D) bf16

// bf16 copies of big-GEMM operands
__device__ __nv_bfloat16 g_qbf[PT*PD];
__device__ __nv_bfloat16 g_kbf[PT*PD];
__device__ __nv_bfloat16 g_vbf[PT*PD];
__device__ __nv_bfloat16 g_wqbf[PD*PD];
__device__ __nv_bfloat16 g_wkbf[PD*PD];
__device__ __nv_bfloat16 g_wvbf[PD*PD];
__device__ __nv_bfloat16 g_wobf[PD*PD];

// ---------------- helpers ----------------
__device__ __forceinline__ uint32_t f2bf2(float lo, float hi) {
    __nv_bfloat162 h = __float22bfloat162_rn(make_float2(lo, hi));
    return *(uint32_t*)&h;
}
__device__ __forceinline__ float2 bf2f(uint32_t r) {
    return __bfloat1622float2(*(__nv_bfloat162*)&r);
}
__device__ __forceinline__ uint32_t smem_u32(const void* p) {
    uint32_t a;
    asm("{ .reg .u64 t; cvta.to.shared.u64 t, %1; cvt.u32.u64 %0, t; }" : "=r"(a) : "l"(p));
    return a;
}
#define CP_ASYNC16(dst, src) \
    asm volatile("cp.async.cg.shared.global [%0], [%1], 16;" :: "r"(dst), "l"(src))
#define CP_COMMIT() asm volatile("cp.async.commit_group;")
#define LDSM4(r0, r1, r2, r3, a) \
    asm volatile("ldmatrix.sync.aligned.m8n8.x4.shared.b16 {%0,%1,%2,%3}, [%4];" \
        : "=r"(r0), "=r"(r1), "=r"(r2), "=r"(r3) : "r"(a))
#define MMA_BF16(acc, af, bfr) \
    asm volatile( \
        "mma.sync.aligned.m16n8k16.row.col.f32.bf16.bf16.f32 " \
        "{%0,%1,%2,%3}, {%4,%5,%6,%7}, {%8,%9}, {%0,%1,%2,%3};\n" \
        : "+f"((acc)[0]), "+f"((acc)[1]), "+f"((acc)[2]), "+f"((acc)[3]) \
        : "r"((af)[0]), "r"((af)[1]), "r"((af)[2]), "r"((af)[3]), \
          "r"((bfr)[0]), "r"((bfr)[1]))

#define PSTR 20

// ================= fp32 -> bf16 (8 floats/thread) =================
__global__ void cvt_kernel(const float* __restrict__ src, __nv_bfloat16* __restrict__ dst) {
    const long i8 = (long)blockIdx.x * blockDim.x + threadIdx.x;
    const float4 v0 = *(const float4*)(src + i8 * 8);
    const float4 v1 = *(const float4*)(src + i8 * 8 + 4);
    uint4 p;
    p.x = f2bf2(v0.x, v0.y); p.y = f2bf2(v0.z, v0.w);
    p.z = f2bf2(v1.x, v1.y); p.w = f2bf2(v1.z, v1.w);
    *(uint4*)(dst + i8 * 8) = p;
}

// ================= big bf16 GEMM: 256x128 tile, 512 threads =================
// C = A @ W^T, A,W bf16 [2048,2048] row-major.
// EPI 0: permute fp32 -> (B,H,L,Dh)
// EPI 1: permute fp32 + bf16 dual store
// EPI 2: permute bf16 only
// EPI 4: bias add fp32 row-major
#define STGA (256*PSTR)   // words
#define STGB (128*PSTR)
#define NST 4
#define BIG_SMEM ((NST*STGA + NST*STGB) * 4)   // 122880

template<int EPI>
__global__ __launch_bounds__(512, 1)
void big_gemm(const __nv_bfloat16* __restrict__ Ag, const __nv_bfloat16* __restrict__ Wg,
              float* __restrict__ Cg, __nv_bfloat16* __restrict__ Cb,
              const float* __restrict__ bias)
{
    extern __shared__ __align__(16) uint32_t sm[];
    const uint32_t sbase = smem_u32(sm);

    const int tid = threadIdx.x;
    const int lane = tid & 31;
    const int warpId = tid >> 5;       // 0..15
    const int g = lane >> 2;
    const int t = lane & 3;
    const int warpM = warpId >> 2;     // 0..3
    const int warpN = warpId & 3;      // 0..3
    const int m0 = blockIdx.y * 256;
    const int n0 = blockIdx.x * 128;

    // A: 1024 granules (16B), 2 per thread; B: 512 granules, 1 per thread
    const int ga0 = tid, ga1 = tid + 512;
    const int ar0 = ga0 >> 2, ac0 = ga0 & 3;
    const int ar1 = ga1 >> 2, ac1 = ga1 & 3;
    const int br  = tid >> 2, bc = tid & 3;
    const uint32_t da0 = (ar0 * PSTR + ac0 * 4) * 4;
    const uint32_t da1 = (ar1 * PSTR + ac1 * 4) * 4;
    const uint32_t db  = (br  * PSTR + bc  * 4) * 4;

    uint32_t aoff[4];
#pragma unroll
    for (int mt = 0; mt < 4; mt++) {
        const int ar = warpM * 64 + mt * 16 + (lane & 15);
        const int ac = (lane >> 4) * 4;
        aoff[mt] = (ar * PSTR + ac) * 4;
    }
    uint32_t boff[2];
#pragma unroll
    for (int p = 0; p < 2; p++) {
        const int brr = warpN * 32 + p * 16 + (lane & 7) + ((lane >> 4) << 3);
        const int bcc = ((lane >> 3) & 1) * 4;
        boff[p] = (brr * PSTR + bcc) * 4;
    }

    float acc[4][4][4];
#pragma unroll
    for (int mt = 0; mt < 4; mt++)
#pragma unroll
        for (int nt = 0; nt < 4; nt++)
#pragma unroll
            for (int i = 0; i < 4; i++) acc[mt][nt][i] = 0.f;

    auto issue = [&](int s) {
        const int st = s & (NST - 1);
        const uint32_t aT = sbase + st * STGA * 4;
        const uint32_t bT = sbase + (NST * STGA + st * STGB) * 4;
        const int k0 = s * 32;
        CP_ASYNC16(aT + da0, Ag + (long)(m0 + ar0) * PD + k0 + ac0 * 8);
        CP_ASYNC16(aT + da1, Ag + (long)(m0 + ar1) * PD + k0 + ac1 * 8);
        CP_ASYNC16(bT + db,  Wg + (long)(n0 + br)  * PD + k0 + bc  * 8);
        CP_COMMIT();
    };

    const int NSTAGE = PD / 32;  // 64
    issue(0);
    issue(1);

    for (int s = 0; s < NSTAGE; s++) {
        if (s + 2 < NSTAGE) { issue(s + 2); asm volatile("cp.async.wait_group 2;"); }
        else if (s + 1 < NSTAGE) { asm volatile("cp.async.wait_group 1;"); }
        else { asm volatile("cp.async.wait_group 0;"); }
        __syncthreads();

        const int st = s & (NST - 1);
        const uint32_t aT = sbase + st * STGA * 4;
        const uint32_t bT = sbase + (NST * STGA + st * STGB) * 4;

#pragma unroll
        for (int kk = 0; kk < 16; kk += 8) {
            uint32_t af[4][4];
#pragma unroll
            for (int mt = 0; mt < 4; mt++)
                LDSM4(af[mt][0], af[mt][1], af[mt][2], af[mt][3], aT + aoff[mt] + kk * 4);
            uint32_t bfr[4][2];
#pragma unroll
            for (int p = 0; p < 2; p++)
                LDSM4(bfr[2*p][0], bfr[2*p][1], bfr[2*p+1][0], bfr[2*p+1][1],
                      bT + boff[p] + kk * 4);
#pragma unroll
            for (int mt = 0; mt < 4; mt++)
#pragma unroll
                for (int nt = 0; nt < 4; nt++)
                    MMA_BF16(acc[mt][nt], af[mt], bfr[nt]);
        }
    }

#pragma unroll
    for (int mt = 0; mt < 4; mt++) {
        const int rL = m0 + warpM*64 + mt*16 + g;
        const int rH = rL + 8;
#pragma unroll
        for (int nt = 0; nt < 4; nt++) {
            const int c = n0 + warpN*32 + nt*8 + t*2;
            float2 vL = make_float2(acc[mt][nt][0], acc[mt][nt][1]);
            float2 vH = make_float2(acc[mt][nt][2], acc[mt][nt][3]);
            if (EPI == 0 || EPI == 1 || EPI == 2) {
                const int h = c >> 8, d = c & 255;
                const int bL = rL >> 8, lL = rL & 255;
                const int bR = rH >> 8, lH = rH & 255;
                const long iL = (((long)(bL*PH + h))*PL + lL)*PDH + d;
                const long iH = (((long)(bR*PH + h))*PL + lH)*PDH + d;
                if (EPI == 0 || EPI == 1) {
                    *(float2*)&Cg[iL] = vL;
                    *(float2*)&Cg[iH] = vH;
                }
                if (EPI == 1 || EPI == 2) {
                    ((uint32_t*)Cb)[iL >> 1] = f2bf2(vL.x, vL.y);
                    ((uint32_t*)Cb)[iH >> 1] = f2bf2(vH.x, vH.y);
                }
            } else { // EPI == 4
                float2 bv = *(const float2*)&bias[c];
                *(float2*)&Cg[(long)rL*PD + c] = make_float2(vL.x + bv.x, vL.y + bv.y);
                *(float2*)&Cg[(long)rH*PD + c] = make_float2(vH.x + bv.x, vH.y + bv.y);
            }
        }
    }
}

// ================= batched bf16 TN GEMM: 128x128 tile, 256 threads =================
// C[z] = A[z] @ B[z]^T, A [M,K] bf16 rm, B [N,K] bf16 rm, K=256.
// EPI 1: plain fp32 store; EPI 2: causal mask -> bf16 store;
// EPI 3: rowsum(A)-divide -> bf16 scatter to (B,L,D).
#define BSTG (128*PSTR)
#define BAT_SMEM (2*NST*BSTG*4)   // 81920

template<int EPI>
__global__ __launch_bounds__(256, 2)
void bat_gemm(const __nv_bfloat16* __restrict__ Ag, const __nv_bfloat16* __restrict__ Bg,
              float* __restrict__ Cg,
              int N, int lda, int ldb,
              long strideA, long strideB, long strideC)
{
    extern __shared__ __align__(16) uint32_t sm[];
    const uint32_t sbase = smem_u32(sm);

    const int tid = threadIdx.x;
    const int lane = tid & 31;
    const int warpId = tid >> 5;
    const int g = lane >> 2;
    const int t = lane & 3;
    const int warpM = warpId >> 2;
    const int warpN = warpId & 3;
    const int m0 = blockIdx.y * 128;
    const int n0 = blockIdx.x * 128;
    const int z  = blockIdx.z;
    const __nv_bfloat16* A  = Ag + (long)z * strideA;
    const __nv_bfloat16* Bm = Bg + (long)z * strideB;

    const int gid0 = tid, gid1 = tid + 256;
    const int row0 = gid0 >> 2, gc0 = gid0 & 3;
    const int row1 = gid1 >> 2, gc1 = gid1 & 3;
    const uint32_t d0 = (row0 * PSTR + gc0 * 4) * 4;
    const uint32_t d1 = (row1 * PSTR + gc1 * 4) * 4;

    uint32_t aoff[4];
#pragma unroll
    for (int mt = 0; mt < 4; mt++) {
        const int ar = warpM * 64 + mt * 16 + (lane & 15);
        const int ac = (lane >> 4) * 4;
        aoff[mt] = (ar * PSTR + ac) * 4;
    }
    uint32_t boff[2];
#pragma unroll
    for (int p = 0; p < 2; p++) {
        const int br = warpN * 32 + p * 16 + (lane & 7) + ((lane >> 4) << 3);
        const int bc = ((lane >> 3) & 1) * 4;
        boff[p] = (br * PSTR + bc) * 4;
    }

    float acc[4][4][4];
#pragma unroll
    for (int mt = 0; mt < 4; mt++)
#pragma unroll
        for (int nt = 0; nt < 4; nt++)
#pragma unroll
            for (int i = 0; i < 4; i++) acc[mt][nt][i] = 0.f;

    float denL[4] = {0.f,0.f,0.f,0.f};
    float denH[4] = {0.f,0.f,0.f,0.f};

    auto issue = [&](int s) {
        const int st = s & (NST - 1);
        const uint32_t aT = sbase + st * BSTG * 4;
        const uint32_t bT = sbase + (NST + st) * BSTG * 4;
        const int k0 = s * 32;
        CP_ASYNC16(aT + d0, A  + (long)(m0 + row0) * lda + k0 + gc0 * 8);
        CP_ASYNC16(aT + d1, A  + (long)(m0 + row1) * lda + k0 + gc1 * 8);
        CP_ASYNC16(bT + d0, Bm + (long)(n0 + row0) * ldb + k0 + gc0 * 8);
        CP_ASYNC16(bT + d1, Bm + (long)(n0 + row1) * ldb + k0 + gc1 * 8);
        CP_COMMIT();
    };

    const int NSTAGE = 256 / 32;  // 8
    issue(0);
    issue(1);

    for (int s = 0; s < NSTAGE; s++) {
        if (s + 2 < NSTAGE) { issue(s + 2); asm volatile("cp.async.wait_group 2;"); }
        else if (s + 1 < NSTAGE) { asm volatile("cp.async.wait_group 1;"); }
        else { asm volatile("cp.async.wait_group 0;"); }
        __syncthreads();

        const int st = s & (NST - 1);
        const uint32_t aT = sbase + st * BSTG * 4;
        const uint32_t bT = sbase + (NST + st) * BSTG * 4;

#pragma unroll
        for (int kk = 0; kk < 16; kk += 8) {
            uint32_t af[4][4];
#pragma unroll
            for (int mt = 0; mt < 4; mt++)
                LDSM4(af[mt][0], af[mt][1], af[mt][2], af[mt][3], aT + aoff[mt] + kk * 4);
            uint32_t bfr[4][2];
#pragma unroll
            for (int p = 0; p < 2; p++)
                LDSM4(bfr[2*p][0], bfr[2*p][1], bfr[2*p+1][0], bfr[2*p+1][1],
                      bT + boff[p] + kk * 4);
            if (EPI == 3) {
#pragma unroll
                for (int mt = 0; mt < 4; mt++) {
                    float2 u0 = bf2f(af[mt][0]), u2 = bf2f(af[mt][2]);
                    float2 u1 = bf2f(af[mt][1]), u3 = bf2f(af[mt][3]);
                    denL[mt] += u0.x + u0.y + u2.x + u2.y;
                    denH[mt] += u1.x + u1.y + u3.x + u3.y;
                }
            }
#pragma unroll
            for (int mt = 0; mt < 4; mt++)
#pragma unroll
                for (int nt = 0; nt < 4; nt++)
                    MMA_BF16(acc[mt][nt], af[mt], bfr[nt]);
        }
    }

    float invL[4], invH[4];
    if (EPI == 3) {
#pragma unroll
        for (int mt = 0; mt < 4; mt++) {
            float dl = denL[mt], dh = denH[mt];
            dl += __shfl_xor_sync(0xffffffffu, dl, 1);
            dl += __shfl_xor_sync(0xffffffffu, dl, 2);
            dh += __shfl_xor_sync(0xffffffffu, dh, 1);
            dh += __shfl_xor_sync(0xffffffffu, dh, 2);
            invL[mt] = 1.0f / fmaxf(dl, 1e-8f);
            invH[mt] = 1.0f / fmaxf(dh, 1e-8f);
        }
    }

#pragma unroll
    for (int mt = 0; mt < 4; mt++) {
        const int rL = m0 + warpM*64 + mt*16 + g;
        const int rH = rL + 8;
#pragma unroll
        for (int nt = 0; nt < 4; nt++) {
            const int c = n0 + warpN*32 + nt*8 + t*2;
            float2 vL = make_float2(acc[mt][nt][0], acc[mt][nt][1]);
            float2 vH = make_float2(acc[mt][nt][2], acc[mt][nt][3]);
            if (EPI == 1) {
                float* cz = Cg + (long)z * strideC;
                *(float2*)&cz[(long)rL*N + c] = vL;
                *(float2*)&cz[(long)rH*N + c] = vH;
            } else if (EPI == 2) {
                uint32_t* cz = (uint32_t*)Cg + ((long)z * strideC >> 1);
                const float wLx = c   <= rL ? vL.x : 0.f;
                const float wLy = c+1 <= rL ? vL.y : 0.f;
                const float wHx = c   <= rH ? vH.x : 0.f;
                const float wHy = c+1 <= rH ? vH.y : 0.f;
                cz[((long)rL*N + c) >> 1] = f2bf2(wLx, wLy);
                cz[((long)rH*N + c) >> 1] = f2bf2(wHx, wHy);
            } else { // EPI == 3: bf16 scatter to (B,L,D)
                const int b = z / PH, h = z % PH;
                uint32_t* cb16 = (uint32_t*)Cg;
                const long iL = ((long)(b*PL + rL))*PD + h*PDH + c;
                const long iH = ((long)(b*PL + rH))*PD + h*PDH + c;
                cb16[iL >> 1] = f2bf2(vL.x*invL[mt], vL.y*invL[mt]);
                cb16[iH >> 1] = f2bf2(vH.x*invH[mt], vH.y*invH[mt]);
            }
        }
    }
}

// ================= V transpose: (b,h)[L][Dh] bf16 -> (b,h)[Dh][L] bf16 =================
__global__ void vt_kernel(const __nv_bfloat16* __restrict__ in, __nv_bfloat16* __restrict__ out) {
    __shared__ __nv_bfloat16 tile[32][33];
    const int z = blockIdx.z;
    const int l0 = blockIdx.x * 32;
    const int d0 = blockIdx.y * 32;
    const int tx = threadIdx.x, ty = threadIdx.y;
    const __nv_bfloat16* src = in + (long)z * PL * PDH;
    __nv_bfloat16* dst = out + (long)z * PDH * PL;
#pragma unroll
    for (int j = 0; j < 4; j++)
        tile[ty*4 + j][tx] = src[(long)(l0 + ty*4 + j) * PDH + d0 + tx];
    __syncthreads();
#pragma unroll
    for (int j = 0; j < 4; j++)
        dst[(long)(d0 + ty*4 + j) * PL + l0 + tx] = tile[tx][ty*4 + j];
}

// ---------------- small kernels ----------------
__global__ void zero_mh_kernel(float* mh) {
    int i = blockIdx.x * blockDim.x + threadIdx.x;
    if (i < PH*PL) mh[i] = 0.f;
}

__global__ void mh_kernel(const float* __restrict__ kv, float* __restrict__ mh) {
    const int h = blockIdx.x, b = blockIdx.y, m = threadIdx.x;
    const float* base = kv + ((long)(b*PH + h) * PL) * PL + m;
    float s = 0.f;
#pragma unroll 4
    for (int l = 0; l < PL; l++) s += base[(long)l * PL];
    atomicAdd(&mh[h*PL + m], s * (1.0f / (float)(PB*PL)));
}

__global__ void cs_kernel(const float* __restrict__ mh, float* __restrict__ cs,
                          const float* __restrict__ alpha_p, const float* __restrict__ beta_p) {
    const int d = threadIdx.x;
    const float a = *alpha_p, bt = *beta_p;
    float c = 0.f;
    for (int h = 0; h < PH; h++) {
        cs[h*PDH + d] = c;
        c = bt * c + a * mh[h*PL + d];
    }
}

// pq = phi(Q*(cs+alpha*(kv-cs))) bf16, pk = phi(K) bf16; 2 elems/thread
__global__ void phi_kernel(const float* __restrict__ Q, const float* __restrict__ K,
                           const float* __restrict__ kv, const float* __restrict__ cs,
                           __nv_bfloat16* __restrict__ pq, __nv_bfloat16* __restrict__ pk,
                           const float* __restrict__ alpha_p) {
    const long gid = (long)blockIdx.x * blockDim.x + threadIdx.x;
    const long idx = gid * 2;
    const float a = *alpha_p;
    const int h = (int)((idx >> 16) & 7);
    const int d = (int)(idx & 255);
    const float2 q2 = *(const float2*)(Q + idx);
    const float2 k2 = *(const float2*)(K + idx);
    const float2 v2 = *(const float2*)(kv + idx);
    const float c0 = cs[h*PDH + d], c1 = cs[h*PDH + d + 1];
    const float qm0 = q2.x * (c0 + a * (v2.x - c0));
    const float qm1 = q2.y * (c1 + a * (v2.y - c1));
    const float p0 = qm0 > 0.f ? qm0 + 1.f : __expf(qm0);
    const float p1 = qm1 > 0.f ? qm1 + 1.f : __expf(qm1);
    const float r0 = k2.x > 0.f ? k2.x + 1.f : __expf(k2.x);
    const float r1 = k2.y > 0.f ? k2.y + 1.f : __expf(k2.y);
    ((uint32_t*)pq)[gid] = f2bf2(p0, p1);
    ((uint32_t*)pk)[gid] = f2bf2(r0, r1);
}

__global__ void ln_kernel(const float* __restrict__ q, const float* __restrict__ o,
                          const float* __restrict__ g, const float* __restrict__ be,
                          float* __restrict__ out) {
    const int tk = blockIdx.x;
    const int tid = threadIdx.x;
    __shared__ float red[256];
    const float* xq = q + (long)tk * PD;
    const float* xo = o + (long)tk * PD;
    float x[8];
    float s = 0.f;
#pragma unroll
    for (int i = 0; i < 8; i++) {
        x[i] = xq[tid + i*256] + xo[tid + i*256];
        s += x[i];
    }
    red[tid] = s; __syncthreads();
    for (int st = 128; st > 0; st >>= 1) {
        if (tid < st) red[tid] += red[tid + st];
        __syncthreads();
    }
    const float mu = red[0] * (1.0f / PD);
    __syncthreads();
    float v = 0.f;
#pragma unroll
    for (int i = 0; i < 8; i++) { const float dd = x[i] - mu; v += dd*dd; }
    red[tid] = v; __syncthreads();
    for (int st = 128; st > 0; st >>= 1) {
        if (tid < st) red[tid] += red[tid + st];
        __syncthreads();
    }
    const float inv = rsqrtf(red[0] * (1.0f / PD) + 1e-5f);
#pragma unroll
    for (int i = 0; i < 8; i++) {
        const int c = tid + i*256;
        out[(long)tk*PD + c] = (x[i] - mu) * inv * g[c] + be[c];
    }
}

// ---------------- launch ----------------
extern "C" void kernel_launch(void* const* d_in, const int* in_sizes, int n_in,
                              void* d_out, int out_size) {
    const float* query = (const float*)d_in[0];
    const float* key   = (const float*)d_in[1];
    const float* value = (const float*)d_in[2];
    const float* Wq    = (const float*)d_in[3];
    const float* Wk    = (const float*)d_in[4];
    const float* Wv    = (const float*)d_in[5];
    const float* Wo    = (const float*)d_in[6];
    const float* bo    = (const float*)d_in[7];
    const float* ln_g  = (const float*)d_in[8];
    const float* ln_b  = (const float*)d_in[9];
    const float* alpha = (const float*)d_in[10];
    const float* beta  = (const float*)d_in[11];
    float* out = (float*)d_out;

    float *Q, *K, *kv, *o, *mh, *cs;
    __nv_bfloat16 *kbhl, *vbhl, *vt, *pq, *pk, *Am, *attnbf;
    __nv_bfloat16 *qbf, *kbf, *vbf, *wqbf, *wkbf, *wvbf, *wobf;
    cudaGetSymbolAddress((void**)&Q,  g_Q);
    cudaGetSymbolAddress((void**)&K,  g_K);
    cudaGetSymbolAddress((void**)&kv, g_kv);
    cudaGetSymbolAddress((void**)&o,  g_o);
    cudaGetSymbolAddress((void**)&mh, g_mh);
    cudaGetSymbolAddress((void**)&cs, g_cs);
    cudaGetSymbolAddress((void**)&kbhl, g_kbhl);
    cudaGetSymbolAddress((void**)&vbhl, g_vbhl);
    cudaGetSymbolAddress((void**)&vt, g_vt);
    cudaGetSymbolAddress((void**)&pq, g_pq);
    cudaGetSymbolAddress((void**)&pk, g_pk);
    cudaGetSymbolAddress((void**)&Am, g_Am);
    cudaGetSymbolAddress((void**)&attnbf, g_attnbf);
    cudaGetSymbolAddress((void**)&qbf, g_qbf);
    cudaGetSymbolAddress((void**)&kbf, g_kbf);
    cudaGetSymbolAddress((void**)&vbf, g_vbf);
    cudaGetSymbolAddress((void**)&wqbf, g_wqbf);
    cudaGetSymbolAddress((void**)&wkbf, g_wkbf);
    cudaGetSymbolAddress((void**)&wvbf, g_wvbf);
    cudaGetSymbolAddress((void**)&wobf, g_wobf);

    cudaFuncSetAttribute(big_gemm<0>, cudaFuncAttributeMaxDynamicSharedMemorySize, BIG_SMEM);
    cudaFuncSetAttribute(big_gemm<1>, cudaFuncAttributeMaxDynamicSharedMemorySize, BIG_SMEM);
    cudaFuncSetAttribute(big_gemm<2>, cudaFuncAttributeMaxDynamicSharedMemorySize, BIG_SMEM);
    cudaFuncSetAttribute(big_gemm<4>, cudaFuncAttributeMaxDynamicSharedMemorySize, BIG_SMEM);
    cudaFuncSetAttribute(bat_gemm<1>, cudaFuncAttributeMaxDynamicSharedMemorySize, BAT_SMEM);
    cudaFuncSetAttribute(bat_gemm<2>, cudaFuncAttributeMaxDynamicSharedMemorySize, BAT_SMEM);
    cudaFuncSetAttribute(bat_gemm<3>, cudaFuncAttributeMaxDynamicSharedMemorySize, BAT_SMEM);

    dim3 gBig(PD/128, PT/256, 1);           // 16 x 8 = 128 CTAs
    dim3 gBat(2, 2, BH);                    // 256 CTAs
    const int CVB = (PT*PD/8) / 256;        // 2048 blocks

    // 0. fp32 -> bf16 conversions
    cvt_kernel<<<CVB, 256>>>(query, qbf);
    cvt_kernel<<<CVB, 256>>>(key,   kbf);
    cvt_kernel<<<CVB, 256>>>(value, vbf);
    cvt_kernel<<<CVB, 256>>>(Wq, wqbf);
    cvt_kernel<<<CVB, 256>>>(Wk, wkbf);
    cvt_kernel<<<CVB, 256>>>(Wv, wvbf);
    cvt_kernel<<<CVB, 256>>>(Wo, wobf);

    // 1. projections
    big_gemm<0><<<gBig, 512, BIG_SMEM>>>(qbf, wqbf, Q, nullptr, nullptr);        // Q fp32
    big_gemm<1><<<gBig, 512, BIG_SMEM>>>(kbf, wkbf, K, kbhl, nullptr);           // K fp32+bf16
    big_gemm<2><<<gBig, 512, BIG_SMEM>>>(vbf, wvbf, nullptr, vbhl, nullptr);     // V bf16 only

    // 1b. V transpose (b,h): [L,Dh] -> [Dh,L]
    vt_kernel<<<dim3(PL/32, PDH/32, BH), dim3(32, 8)>>>(vbhl, vt);

    // 2. kv = K @ V^T per (b,h), fp32 out
    bat_gemm<1><<<gBat, 256, BAT_SMEM>>>(kbhl, vbhl, kv, PL, PDH, PDH,
                                         (long)PL*PDH, (long)PL*PDH, (long)PL*PL);

    // 3. mh = mean over (b,l) of kv
    zero_mh_kernel<<<(PH*PL + 255)/256, 256>>>(mh);
    mh_kernel<<<dim3(PH, PB), 256>>>(kv, mh);

    // 4. cs scan over heads
    cs_kernel<<<1, 256>>>(mh, cs, alpha, beta);

    // 5. pq/pk (bf16 out)
    phi_kernel<<<(BH*PL*PDH/2) / 256, 256>>>(Q, K, kv, cs, pq, pk, alpha);

    // 6. A = tril(pq @ pk^T), bf16 out
    bat_gemm<2><<<gBat, 256, BAT_SMEM>>>(pq, pk, (float*)Am, PL, PDH, PDH,
                                         (long)PL*PDH, (long)PL*PDH, (long)PL*PL);

    // 7. attn = (A @ V) / rowsum(A) -> bf16 (B,L,D)
    bat_gemm<3><<<gBat, 256, BAT_SMEM>>>(Am, vt, (float*)attnbf, PDH, PL, PL,
                                         (long)PL*PL, (long)PDH*PL, 0);

    // 8. o = attn @ Wo^T + bo
    big_gemm<4><<<gBig, 512, BIG_SMEM>>>(attnbf, wobf, o, nullptr, bo);

    // 9. residual + layernorm
    ln_kernel<<<PT, 256>>>(query, o, ln_g, ln_b, out);
}

// round 7
// speedup vs baseline: 6.1701x; 1.0142x over previous
#include <cuda_runtime.h>
#include <cuda_bf16.h>
#include <math.h>
#include <stdint.h>

// Problem constants
#define PB 8
#define PL 256
#define PD 2048
#define PH 8
#define PDH 256
#define PT (PB*PL)
#define BH (PB*PH)

// ---------------- scratch ----------------
__device__ float g_Q[BH*PL*PDH];          // fp32 Q (B,H,L,Dh) for phi
__device__ float g_kv[BH*PL*PL];          // fp32 kv
__device__ float g_o[PT*PD];
__device__ float g_mh[PH*PL];
__device__ float g_cs[PH*PDH];

__device__ __nv_bfloat16 g_kbhl[BH*PL*PDH];   // K bf16 (B,H,L,Dh)
__device__ __nv_bfloat16 g_vbhl[BH*PL*PDH];   // V bf16 (B,H,L,Dh)
__device__ __nv_bfloat16 g_vt[BH*PDH*PL];     // V^T bf16 (B,H,Dh,L)
__device__ __nv_bfloat16 g_pq[BH*PL*PDH];
__device__ __nv_bfloat16 g_pk[BH*PL*PDH];
__device__ __nv_bfloat16 g_Am[BH*PL*PL];      // causal A bf16
__device__ __nv_bfloat16 g_attnbf[PT*PD];     // attn (B,L,D) bf16

// bf16 copies of big-GEMM operands
__device__ __nv_bfloat16 g_qbf[PT*PD];
__device__ __nv_bfloat16 g_kbf[PT*PD];
__device__ __nv_bfloat16 g_vbf[PT*PD];
__device__ __nv_bfloat16 g_wqbf[PD*PD];
__device__ __nv_bfloat16 g_wkbf[PD*PD];
__device__ __nv_bfloat16 g_wvbf[PD*PD];
__device__ __nv_bfloat16 g_wobf[PD*PD];

// ---------------- helpers ----------------
__device__ __forceinline__ uint32_t f2bf2(float lo, float hi) {
    __nv_bfloat162 h = __float22bfloat162_rn(make_float2(lo, hi));
    return *(uint32_t*)&h;
}
__device__ __forceinline__ float2 bf2f(uint32_t r) {
    return __bfloat1622float2(*(__nv_bfloat162*)&r);
}
__device__ __forceinline__ float phif(float x) {
    return x > 0.f ? x + 1.f : __expf(x);
}
__device__ __forceinline__ uint32_t smem_u32(const void* p) {
    uint32_t a;
    asm("{ .reg .u64 t; cvta.to.shared.u64 t, %1; cvt.u32.u64 %0, t; }" : "=r"(a) : "l"(p));
    return a;
}
#define CP_ASYNC16(dst, src) \
    asm volatile("cp.async.cg.shared.global [%0], [%1], 16;" :: "r"(dst), "l"(src))
#define CP_COMMIT() asm volatile("cp.async.commit_group;")
#define LDSM4(r0, r1, r2, r3, a) \
    asm volatile("ldmatrix.sync.aligned.m8n8.x4.shared.b16 {%0,%1,%2,%3}, [%4];" \
        : "=r"(r0), "=r"(r1), "=r"(r2), "=r"(r3) : "r"(a))
#define MMA_BF16(acc, af, bfr) \
    asm volatile( \
        "mma.sync.aligned.m16n8k16.row.col.f32.bf16.bf16.f32 " \
        "{%0,%1,%2,%3}, {%4,%5,%6,%7}, {%8,%9}, {%0,%1,%2,%3};\n" \
        : "+f"((acc)[0]), "+f"((acc)[1]), "+f"((acc)[2]), "+f"((acc)[3]) \
        : "r"((af)[0]), "r"((af)[1]), "r"((af)[2]), "r"((af)[3]), \
          "r"((bfr)[0]), "r"((bfr)[1]))

#define PSTR 20

// ================= fp32 -> bf16 (16 floats/thread) =================
__global__ void cvt_kernel(const float* __restrict__ src, __nv_bfloat16* __restrict__ dst) {
    const long i = ((long)blockIdx.x * blockDim.x + threadIdx.x) * 16;
    const float4 v0 = *(const float4*)(src + i);
    const float4 v1 = *(const float4*)(src + i + 4);
    const float4 v2 = *(const float4*)(src + i + 8);
    const float4 v3 = *(const float4*)(src + i + 12);
    uint4 p0, p1;
    p0.x = f2bf2(v0.x, v0.y); p0.y = f2bf2(v0.z, v0.w);
    p0.z = f2bf2(v1.x, v1.y); p0.w = f2bf2(v1.z, v1.w);
    p1.x = f2bf2(v2.x, v2.y); p1.y = f2bf2(v2.z, v2.w);
    p1.z = f2bf2(v3.x, v3.y); p1.w = f2bf2(v3.z, v3.w);
    *(uint4*)(dst + i) = p0;
    *(uint4*)(dst + i + 8) = p1;
}

// ================= big bf16 GEMM: 256x128 tile, 512 threads =================
// C = A @ W^T, A,W bf16 [2048,2048] row-major.
// EPI 0: permute fp32 -> (B,H,L,Dh)
// EPI 2: permute bf16 only
// EPI 4: bias add fp32 row-major
// EPI 5: K-proj: permute bf16 (Cb) + phi(x) bf16 (Cb2)
#define STGA (256*PSTR)   // words
#define STGB (128*PSTR)
#define NSTB 6
#define BIG_SMEM (NSTB*(STGA + STGB)*4)   // 184320

template<int EPI>
__global__ __launch_bounds__(512, 1)
void big_gemm(const __nv_bfloat16* __restrict__ Ag, const __nv_bfloat16* __restrict__ Wg,
              float* __restrict__ Cg, __nv_bfloat16* __restrict__ Cb,
              __nv_bfloat16* __restrict__ Cb2, const float* __restrict__ bias)
{
    extern __shared__ __align__(16) uint32_t sm[];
    const uint32_t sbase = smem_u32(sm);

    const int tid = threadIdx.x;
    const int lane = tid & 31;
    const int warpId = tid >> 5;       // 0..15
    const int g = lane >> 2;
    const int t = lane & 3;
    const int warpM = warpId >> 2;     // 0..3
    const int warpN = warpId & 3;      // 0..3
    const int m0 = blockIdx.y * 256;
    const int n0 = blockIdx.x * 128;

    const int ga0 = tid, ga1 = tid + 512;
    const int ar0 = ga0 >> 2, ac0 = ga0 & 3;
    const int ar1 = ga1 >> 2, ac1 = ga1 & 3;
    const int br  = tid >> 2, bc = tid & 3;
    const uint32_t da0 = (ar0 * PSTR + ac0 * 4) * 4;
    const uint32_t da1 = (ar1 * PSTR + ac1 * 4) * 4;
    const uint32_t db  = (br  * PSTR + bc  * 4) * 4;

    uint32_t aoff[4];
#pragma unroll
    for (int mt = 0; mt < 4; mt++) {
        const int ar = warpM * 64 + mt * 16 + (lane & 15);
        const int ac = (lane >> 4) * 4;
        aoff[mt] = (ar * PSTR + ac) * 4;
    }
    uint32_t boff[2];
#pragma unroll
    for (int p = 0; p < 2; p++) {
        const int brr = warpN * 32 + p * 16 + (lane & 7) + ((lane >> 4) << 3);
        const int bcc = ((lane >> 3) & 1) * 4;
        boff[p] = (brr * PSTR + bcc) * 4;
    }

    float acc[4][4][4];
#pragma unroll
    for (int mt = 0; mt < 4; mt++)
#pragma unroll
        for (int nt = 0; nt < 4; nt++)
#pragma unroll
            for (int i = 0; i < 4; i++) acc[mt][nt][i] = 0.f;

    auto issue = [&](int s) {
        const int st = s % NSTB;
        const uint32_t aT = sbase + st * STGA * 4;
        const uint32_t bT = sbase + (NSTB * STGA + st * STGB) * 4;
        const int k0 = s * 32;
        CP_ASYNC16(aT + da0, Ag + (long)(m0 + ar0) * PD + k0 + ac0 * 8);
        CP_ASYNC16(aT + da1, Ag + (long)(m0 + ar1) * PD + k0 + ac1 * 8);
        CP_ASYNC16(bT + db,  Wg + (long)(n0 + br)  * PD + k0 + bc  * 8);
        CP_COMMIT();
    };

    const int NSTAGE = PD / 32;  // 64
    issue(0); issue(1); issue(2);

    for (int s = 0; s < NSTAGE; s++) {
        if (s + 3 < NSTAGE) { issue(s + 3); asm volatile("cp.async.wait_group 3;"); }
        else if (s + 2 < NSTAGE) { asm volatile("cp.async.wait_group 2;"); }
        else if (s + 1 < NSTAGE) { asm volatile("cp.async.wait_group 1;"); }
        else { asm volatile("cp.async.wait_group 0;"); }
        __syncthreads();

        const int st = s % NSTB;
        const uint32_t aT = sbase + st * STGA * 4;
        const uint32_t bT = sbase + (NSTB * STGA + st * STGB) * 4;

#pragma unroll
        for (int kk = 0; kk < 16; kk += 8) {
            uint32_t af[4][4];
#pragma unroll
            for (int mt = 0; mt < 4; mt++)
                LDSM4(af[mt][0], af[mt][1], af[mt][2], af[mt][3], aT + aoff[mt] + kk * 4);
            uint32_t bfr[4][2];
#pragma unroll
            for (int p = 0; p < 2; p++)
                LDSM4(bfr[2*p][0], bfr[2*p][1], bfr[2*p+1][0], bfr[2*p+1][1],
                      bT + boff[p] + kk * 4);
#pragma unroll
            for (int mt = 0; mt < 4; mt++)
#pragma unroll
                for (int nt = 0; nt < 4; nt++)
                    MMA_BF16(acc[mt][nt], af[mt], bfr[nt]);
        }
    }

#pragma unroll
    for (int mt = 0; mt < 4; mt++) {
        const int rL = m0 + warpM*64 + mt*16 + g;
        const int rH = rL + 8;
#pragma unroll
        for (int nt = 0; nt < 4; nt++) {
            const int c = n0 + warpN*32 + nt*8 + t*2;
            float2 vL = make_float2(acc[mt][nt][0], acc[mt][nt][1]);
            float2 vH = make_float2(acc[mt][nt][2], acc[mt][nt][3]);
            if (EPI == 0 || EPI == 2 || EPI == 5) {
                const int h = c >> 8, d = c & 255;
                const int bL = rL >> 8, lL = rL & 255;
                const int bR = rH >> 8, lH = rH & 255;
                const long iL = (((long)(bL*PH + h))*PL + lL)*PDH + d;
                const long iH = (((long)(bR*PH + h))*PL + lH)*PDH + d;
                if (EPI == 0) {
                    *(float2*)&Cg[iL] = vL;
                    *(float2*)&Cg[iH] = vH;
                }
                if (EPI == 2 || EPI == 5) {
                    ((uint32_t*)Cb)[iL >> 1] = f2bf2(vL.x, vL.y);
                    ((uint32_t*)Cb)[iH >> 1] = f2bf2(vH.x, vH.y);
                }
                if (EPI == 5) {
                    ((uint32_t*)Cb2)[iL >> 1] = f2bf2(phif(vL.x), phif(vL.y));
                    ((uint32_t*)Cb2)[iH >> 1] = f2bf2(phif(vH.x), phif(vH.y));
                }
            } else { // EPI == 4
                float2 bv = *(const float2*)&bias[c];
                *(float2*)&Cg[(long)rL*PD + c] = make_float2(vL.x + bv.x, vL.y + bv.y);
                *(float2*)&Cg[(long)rH*PD + c] = make_float2(vH.x + bv.x, vH.y + bv.y);
            }
        }
    }
}

// ================= batched bf16 TN GEMM: 128x128 tile, 256 threads =================
// C[z] = A[z] @ B[z]^T, K=256.
// EPI 1: fp32 store + fused column-mean atomics into mh
// EPI 2: causal mask -> bf16 store
// EPI 3: rowsum(A)-divide -> bf16 scatter to (B,L,D)
#define BSTG (128*PSTR)
#define NSTS 4
#define BAT_SMEM (2*NSTS*BSTG*4)   // 81920

template<int EPI>
__global__ __launch_bounds__(256, 2)
void bat_gemm(const __nv_bfloat16* __restrict__ Ag, const __nv_bfloat16* __restrict__ Bg,
              float* __restrict__ Cg, float* __restrict__ mhp,
              int N, int lda, int ldb,
              long strideA, long strideB, long strideC)
{
    extern __shared__ __align__(16) uint32_t sm[];
    const uint32_t sbase = smem_u32(sm);
    __shared__ float colsum[128];

    const int tid = threadIdx.x;
    const int lane = tid & 31;
    const int warpId = tid >> 5;
    const int g = lane >> 2;
    const int t = lane & 3;
    const int warpM = warpId >> 2;
    const int warpN = warpId & 3;
    const int m0 = blockIdx.y * 128;
    const int n0 = blockIdx.x * 128;
    const int z  = blockIdx.z;
    const __nv_bfloat16* A  = Ag + (long)z * strideA;
    const __nv_bfloat16* Bm = Bg + (long)z * strideB;

    if (EPI == 1) {
        if (tid < 128) colsum[tid] = 0.f;
    }

    const int gid0 = tid, gid1 = tid + 256;
    const int row0 = gid0 >> 2, gc0 = gid0 & 3;
    const int row1 = gid1 >> 2, gc1 = gid1 & 3;
    const uint32_t d0 = (row0 * PSTR + gc0 * 4) * 4;
    const uint32_t d1 = (row1 * PSTR + gc1 * 4) * 4;

    uint32_t aoff[4];
#pragma unroll
    for (int mt = 0; mt < 4; mt++) {
        const int ar = warpM * 64 + mt * 16 + (lane & 15);
        const int ac = (lane >> 4) * 4;
        aoff[mt] = (ar * PSTR + ac) * 4;
    }
    uint32_t boff[2];
#pragma unroll
    for (int p = 0; p < 2; p++) {
        const int br = warpN * 32 + p * 16 + (lane & 7) + ((lane >> 4) << 3);
        const int bc = ((lane >> 3) & 1) * 4;
        boff[p] = (br * PSTR + bc) * 4;
    }

    float acc[4][4][4];
#pragma unroll
    for (int mt = 0; mt < 4; mt++)
#pragma unroll
        for (int nt = 0; nt < 4; nt++)
#pragma unroll
            for (int i = 0; i < 4; i++) acc[mt][nt][i] = 0.f;

    float denL[4] = {0.f,0.f,0.f,0.f};
    float denH[4] = {0.f,0.f,0.f,0.f};

    auto issue = [&](int s) {
        const int st = s & (NSTS - 1);
        const uint32_t aT = sbase + st * BSTG * 4;
        const uint32_t bT = sbase + (NSTS + st) * BSTG * 4;
        const int k0 = s * 32;
        CP_ASYNC16(aT + d0, A  + (long)(m0 + row0) * lda + k0 + gc0 * 8);
        CP_ASYNC16(aT + d1, A  + (long)(m0 + row1) * lda + k0 + gc1 * 8);
        CP_ASYNC16(bT + d0, Bm + (long)(n0 + row0) * ldb + k0 + gc0 * 8);
        CP_ASYNC16(bT + d1, Bm + (long)(n0 + row1) * ldb + k0 + gc1 * 8);
        CP_COMMIT();
    };

    const int NSTAGE = 256 / 32;  // 8
    issue(0);
    issue(1);

    for (int s = 0; s < NSTAGE; s++) {
        if (s + 2 < NSTAGE) { issue(s + 2); asm volatile("cp.async.wait_group 2;"); }
        else if (s + 1 < NSTAGE) { asm volatile("cp.async.wait_group 1;"); }
        else { asm volatile("cp.async.wait_group 0;"); }
        __syncthreads();

        const int st = s & (NSTS - 1);
        const uint32_t aT = sbase + st * BSTG * 4;
        const uint32_t bT = sbase + (NSTS + st) * BSTG * 4;

#pragma unroll
        for (int kk = 0; kk < 16; kk += 8) {
            uint32_t af[4][4];
#pragma unroll
            for (int mt = 0; mt < 4; mt++)
                LDSM4(af[mt][0], af[mt][1], af[mt][2], af[mt][3], aT + aoff[mt] + kk * 4);
            uint32_t bfr[4][2];
#pragma unroll
            for (int p = 0; p < 2; p++)
                LDSM4(bfr[2*p][0], bfr[2*p][1], bfr[2*p+1][0], bfr[2*p+1][1],
                      bT + boff[p] + kk * 4);
            if (EPI == 3) {
#pragma unroll
                for (int mt = 0; mt < 4; mt++) {
                    float2 u0 = bf2f(af[mt][0]), u2 = bf2f(af[mt][2]);
                    float2 u1 = bf2f(af[mt][1]), u3 = bf2f(af[mt][3]);
                    denL[mt] += u0.x + u0.y + u2.x + u2.y;
                    denH[mt] += u1.x + u1.y + u3.x + u3.y;
                }
            }
#pragma unroll
            for (int mt = 0; mt < 4; mt++)
#pragma unroll
                for (int nt = 0; nt < 4; nt++)
                    MMA_BF16(acc[mt][nt], af[mt], bfr[nt]);
        }
    }

    float invL[4], invH[4];
    if (EPI == 3) {
#pragma unroll
        for (int mt = 0; mt < 4; mt++) {
            float dl = denL[mt], dh = denH[mt];
            dl += __shfl_xor_sync(0xffffffffu, dl, 1);
            dl += __shfl_xor_sync(0xffffffffu, dl, 2);
            dh += __shfl_xor_sync(0xffffffffu, dh, 1);
            dh += __shfl_xor_sync(0xffffffffu, dh, 2);
            invL[mt] = 1.0f / fmaxf(dl, 1e-8f);
            invH[mt] = 1.0f / fmaxf(dh, 1e-8f);
        }
    }
    if (EPI == 1) __syncthreads();  // colsum zeroing visible

#pragma unroll
    for (int mt = 0; mt < 4; mt++) {
        const int rL = m0 + warpM*64 + mt*16 + g;
        const int rH = rL + 8;
#pragma unroll
        for (int nt = 0; nt < 4; nt++) {
            const int c = n0 + warpN*32 + nt*8 + t*2;
            float2 vL = make_float2(acc[mt][nt][0], acc[mt][nt][1]);
            float2 vH = make_float2(acc[mt][nt][2], acc[mt][nt][3]);
            if (EPI == 1) {
                float* cz = Cg + (long)z * strideC;
                *(float2*)&cz[(long)rL*N + c] = vL;
                *(float2*)&cz[(long)rH*N + c] = vH;
            } else if (EPI == 2) {
                uint32_t* cz = (uint32_t*)Cg + ((long)z * strideC >> 1);
                const float wLx = c   <= rL ? vL.x : 0.f;
                const float wLy = c+1 <= rL ? vL.y : 0.f;
                const float wHx = c   <= rH ? vH.x : 0.f;
                const float wHy = c+1 <= rH ? vH.y : 0.f;
                cz[((long)rL*N + c) >> 1] = f2bf2(wLx, wLy);
                cz[((long)rH*N + c) >> 1] = f2bf2(wHx, wHy);
            } else { // EPI == 3: bf16 scatter to (B,L,D)
                const int b = z / PH, h = z % PH;
                uint32_t* cb16 = (uint32_t*)Cg;
                const long iL = ((long)(b*PL + rL))*PD + h*PDH + c;
                const long iH = ((long)(b*PL + rH))*PD + h*PDH + c;
                cb16[iL >> 1] = f2bf2(vL.x*invL[mt], vL.y*invL[mt]);
                cb16[iH >> 1] = f2bf2(vH.x*invH[mt], vH.y*invH[mt]);
            }
        }
    }

    if (EPI == 1) {
        // column sums of this CTA's 128x128 tile -> mh atomics
#pragma unroll
        for (int nt = 0; nt < 4; nt++) {
            float s0 = 0.f, s1 = 0.f;
#pragma unroll
            for (int mt = 0; mt < 4; mt++) {
                s0 += acc[mt][nt][0] + acc[mt][nt][2];
                s1 += acc[mt][nt][1] + acc[mt][nt][3];
            }
            const int cl = warpN*32 + nt*8 + t*2;
            atomicAdd(&colsum[cl],   s0);
            atomicAdd(&colsum[cl+1], s1);
        }
        __syncthreads();
        if (tid < 128) {
            const int h = z & 7;
            atomicAdd(&mhp[h*PL + n0 + tid], colsum[tid] * (1.0f / (float)(PB*PL)));
        }
    }
}

// ================= V transpose =================
__global__ void vt_kernel(const __nv_bfloat16* __restrict__ in, __nv_bfloat16* __restrict__ out) {
    __shared__ __nv_bfloat16 tile[32][33];
    const int z = blockIdx.z;
    const int l0 = blockIdx.x * 32;
    const int d0 = blockIdx.y * 32;
    const int tx = threadIdx.x, ty = threadIdx.y;
    const __nv_bfloat16* src = in + (long)z * PL * PDH;
    __nv_bfloat16* dst = out + (long)z * PDH * PL;
#pragma unroll
    for (int j = 0; j < 4; j++)
        tile[ty*4 + j][tx] = src[(long)(l0 + ty*4 + j) * PDH + d0 + tx];
    __syncthreads();
#pragma unroll
    for (int j = 0; j < 4; j++)
        dst[(long)(d0 + ty*4 + j) * PL + l0 + tx] = tile[tx][ty*4 + j];
}

// ---------------- small kernels ----------------
__global__ void zero_mh_kernel(float* mh) {
    int i = blockIdx.x * blockDim.x + threadIdx.x;
    if (i < PH*PL) mh[i] = 0.f;
}

__global__ void cs_kernel(const float* __restrict__ mh, float* __restrict__ cs,
                          const float* __restrict__ alpha_p, const float* __restrict__ beta_p) {
    const int d = threadIdx.x;
    const float a = *alpha_p, bt = *beta_p;
    float c = 0.f;
    for (int h = 0; h < PH; h++) {
        cs[h*PDH + d] = c;
        c = bt * c + a * mh[h*PL + d];
    }
}

// pq = phi(Q*(cs+alpha*(kv-cs))) bf16; 2 elems/thread
__global__ void phi_kernel(const float* __restrict__ Q,
                           const float* __restrict__ kv, const float* __restrict__ cs,
                           __nv_bfloat16* __restrict__ pq,
                           const float* __restrict__ alpha_p) {
    const long gid = (long)blockIdx.x * blockDim.x + threadIdx.x;
    const long idx = gid * 2;
    const float a = *alpha_p;
    const int h = (int)((idx >> 16) & 7);
    const int d = (int)(idx & 255);
    const float2 q2 = *(const float2*)(Q + idx);
    const float2 v2 = *(const float2*)(kv + idx);
    const float c0 = cs[h*PDH + d], c1 = cs[h*PDH + d + 1];
    const float qm0 = q2.x * (c0 + a * (v2.x - c0));
    const float qm1 = q2.y * (c1 + a * (v2.y - c1));
    ((uint32_t*)pq)[gid] = f2bf2(phif(qm0), phif(qm1));
}

__global__ void ln_kernel(const float* __restrict__ q, const float* __restrict__ o,
                          const float* __restrict__ g, const float* __restrict__ be,
                          float* __restrict__ out) {
    const int tk = blockIdx.x;
    const int tid = threadIdx.x;
    __shared__ float red[256];
    const float* xq = q + (long)tk * PD;
    const float* xo = o + (long)tk * PD;
    float x[8];
    float s = 0.f;
#pragma unroll
    for (int i = 0; i < 8; i++) {
        x[i] = xq[tid + i*256] + xo[tid + i*256];
        s += x[i];
    }
    red[tid] = s; __syncthreads();
    for (int st = 128; st > 0; st >>= 1) {
        if (tid < st) red[tid] += red[tid + st];
        __syncthreads();
    }
    const float mu = red[0] * (1.0f / PD);
    __syncthreads();
    float v = 0.f;
#pragma unroll
    for (int i = 0; i < 8; i++) { const float dd = x[i] - mu; v += dd*dd; }
    red[tid] = v; __syncthreads();
    for (int st = 128; st > 0; st >>= 1) {
        if (tid < st) red[tid] += red[tid + st];
        __syncthreads();
    }
    const float inv = rsqrtf(red[0] * (1.0f / PD) + 1e-5f);
#pragma unroll
    for (int i = 0; i < 8; i++) {
        const int c = tid + i*256;
        out[(long)tk*PD + c] = (x[i] - mu) * inv * g[c] + be[c];
    }
}

// ---------------- launch ----------------
extern "C" void kernel_launch(void* const* d_in, const int* in_sizes, int n_in,
                              void* d_out, int out_size) {
    const float* query = (const float*)d_in[0];
    const float* key   = (const float*)d_in[1];
    const float* value = (const float*)d_in[2];
    const float* Wq    = (const float*)d_in[3];
    const float* Wk    = (const float*)d_in[4];
    const float* Wv    = (const float*)d_in[5];
    const float* Wo    = (const float*)d_in[6];
    const float* bo    = (const float*)d_in[7];
    const float* ln_g  = (const float*)d_in[8];
    const float* ln_b  = (const float*)d_in[9];
    const float* alpha = (const float*)d_in[10];
    const float* beta  = (const float*)d_in[11];
    float* out = (float*)d_out;

    float *Q, *kv, *o, *mh, *cs;
    __nv_bfloat16 *kbhl, *vbhl, *vt, *pq, *pk, *Am, *attnbf;
    __nv_bfloat16 *qbf, *kbf, *vbf, *wqbf, *wkbf, *wvbf, *wobf;
    cudaGetSymbolAddress((void**)&Q,  g_Q);
    cudaGetSymbolAddress((void**)&kv, g_kv);
    cudaGetSymbolAddress((void**)&o,  g_o);
    cudaGetSymbolAddress((void**)&mh, g_mh);
    cudaGetSymbolAddress((void**)&cs, g_cs);
    cudaGetSymbolAddress((void**)&kbhl, g_kbhl);
    cudaGetSymbolAddress((void**)&vbhl, g_vbhl);
    cudaGetSymbolAddress((void**)&vt, g_vt);
    cudaGetSymbolAddress((void**)&pq, g_pq);
    cudaGetSymbolAddress((void**)&pk, g_pk);
    cudaGetSymbolAddress((void**)&Am, g_Am);
    cudaGetSymbolAddress((void**)&attnbf, g_attnbf);
    cudaGetSymbolAddress((void**)&qbf, g_qbf);
    cudaGetSymbolAddress((void**)&kbf, g_kbf);
    cudaGetSymbolAddress((void**)&vbf, g_vbf);
    cudaGetSymbolAddress((void**)&wqbf, g_wqbf);
    cudaGetSymbolAddress((void**)&wkbf, g_wkbf);
    cudaGetSymbolAddress((void**)&wvbf, g_wvbf);
    cudaGetSymbolAddress((void**)&wobf, g_wobf);

    cudaFuncSetAttribute(big_gemm<0>, cudaFuncAttributeMaxDynamicSharedMemorySize, BIG_SMEM);
    cudaFuncSetAttribute(big_gemm<2>, cudaFuncAttributeMaxDynamicSharedMemorySize, BIG_SMEM);
    cudaFuncSetAttribute(big_gemm<4>, cudaFuncAttributeMaxDynamicSharedMemorySize, BIG_SMEM);
    cudaFuncSetAttribute(big_gemm<5>, cudaFuncAttributeMaxDynamicSharedMemorySize, BIG_SMEM);
    cudaFuncSetAttribute(bat_gemm<1>, cudaFuncAttributeMaxDynamicSharedMemorySize, BAT_SMEM);
    cudaFuncSetAttribute(bat_gemm<2>, cudaFuncAttributeMaxDynamicSharedMemorySize, BAT_SMEM);
    cudaFuncSetAttribute(bat_gemm<3>, cudaFuncAttributeMaxDynamicSharedMemorySize, BAT_SMEM);

    dim3 gBig(PD/128, PT/256, 1);           // 16 x 8 = 128 CTAs
    dim3 gBat(2, 2, BH);                    // 256 CTAs
    const int CVB = (PT*PD/16) / 256;       // 1024 blocks

    // 0. fp32 -> bf16 conversions + mh zero
    zero_mh_kernel<<<(PH*PL + 255)/256, 256>>>(mh);
    cvt_kernel<<<CVB, 256>>>(query, qbf);
    cvt_kernel<<<CVB, 256>>>(key,   kbf);
    cvt_kernel<<<CVB, 256>>>(value, vbf);
    cvt_kernel<<<CVB, 256>>>(Wq, wqbf);
    cvt_kernel<<<CVB, 256>>>(Wk, wkbf);
    cvt_kernel<<<CVB, 256>>>(Wv, wvbf);
    cvt_kernel<<<CVB, 256>>>(Wo, wobf);

    // 1. projections
    big_gemm<0><<<gBig, 512, BIG_SMEM>>>(qbf, wqbf, Q, nullptr, nullptr, nullptr);       // Q fp32
    big_gemm<5><<<gBig, 512, BIG_SMEM>>>(kbf, wkbf, nullptr, kbhl, pk, nullptr);         // K bf16 + phi(K)
    big_gemm<2><<<gBig, 512, BIG_SMEM>>>(vbf, wvbf, nullptr, vbhl, nullptr, nullptr);    // V bf16

    // 1b. V transpose
    vt_kernel<<<dim3(PL/32, PDH/32, BH), dim3(32, 8)>>>(vbhl, vt);

    // 2. kv = K @ V^T per (b,h), fp32 out + fused column-mean -> mh
    bat_gemm<1><<<gBat, 256, BAT_SMEM>>>(kbhl, vbhl, kv, mh, PL, PDH, PDH,
                                         (long)PL*PDH, (long)PL*PDH, (long)PL*PL);

    // 3. cs scan over heads
    cs_kernel<<<1, 256>>>(mh, cs, alpha, beta);

    // 4. pq (bf16)
    phi_kernel<<<(BH*PL*PDH/2) / 256, 256>>>(Q, kv, cs, pq, alpha);

    // 5. A = tril(pq @ pk^T), bf16 out
    bat_gemm<2><<<gBat, 256, BAT_SMEM>>>(pq, pk, (float*)Am, nullptr, PL, PDH, PDH,
                                         (long)PL*PDH, (long)PL*PDH, (long)PL*PL);

    // 6. attn = (A @ V) / rowsum(A) -> bf16 (B,L,D)
    bat_gemm<3><<<gBat, 256, BAT_SMEM>>>(Am, vt, (float*)attnbf, nullptr, PDH, PL, PL,
                                         (long)PL*PL, (long)PDH*PL, 0);

    // 7. o = attn @ Wo^T + bo
    big_gemm<4><<<gBig, 512, BIG_SMEM>>>(attnbf, wobf, o, nullptr, nullptr, bo);

    // 8. residual + layernorm
    ln_kernel<<<PT, 256>>>(query, o, ln_g, ln_b, out);
}

// round 8
// speedup vs baseline: 6.2896x; 1.0194x over previous
#include <cuda_runtime.h>
#include <cuda_bf16.h>
#include <math.h>
#include <stdint.h>

// Problem constants
#define PB 8
#define PL 256
#define PD 2048
#define PH 8
#define PDH 256
#define PT (PB*PL)
#define BH (PB*PH)

// ---------------- scratch ----------------
__device__ float g_Q[BH*PL*PDH];
__device__ float g_kv[BH*PL*PL];
__device__ float g_o[PT*PD];
__device__ float g_mh[PH*PL];
__device__ float g_cs[PH*PDH];

__device__ __nv_bfloat16 g_kbhl[BH*PL*PDH];
__device__ __nv_bfloat16 g_vbhl[BH*PL*PDH];
__device__ __nv_bfloat16 g_vt[BH*PDH*PL];
__device__ __nv_bfloat16 g_pq[BH*PL*PDH];
__device__ __nv_bfloat16 g_pk[BH*PL*PDH];
__device__ __nv_bfloat16 g_Am[BH*PL*PL];
__device__ __nv_bfloat16 g_attnbf[PT*PD];

__device__ __nv_bfloat16 g_qbf[PT*PD];
__device__ __nv_bfloat16 g_kbf[PT*PD];
__device__ __nv_bfloat16 g_vbf[PT*PD];
__device__ __nv_bfloat16 g_wqbf[PD*PD];
__device__ __nv_bfloat16 g_wkbf[PD*PD];
__device__ __nv_bfloat16 g_wvbf[PD*PD];
__device__ __nv_bfloat16 g_wobf[PD*PD];

// ---------------- helpers ----------------
__device__ __forceinline__ uint32_t f2bf2(float lo, float hi) {
    __nv_bfloat162 h = __float22bfloat162_rn(make_float2(lo, hi));
    return *(uint32_t*)&h;
}
__device__ __forceinline__ float2 bf2f(uint32_t r) {
    return __bfloat1622float2(*(__nv_bfloat162*)&r);
}
__device__ __forceinline__ float phif(float x) {
    return x > 0.f ? x + 1.f : __expf(x);
}
__device__ __forceinline__ uint32_t smem_u32(const void* p) {
    uint32_t a;
    asm("{ .reg .u64 t; cvta.to.shared.u64 t, %1; cvt.u32.u64 %0, t; }" : "=r"(a) : "l"(p));
    return a;
}
#define CP_ASYNC16(dst, src) \
    asm volatile("cp.async.cg.shared.global [%0], [%1], 16;" :: "r"(dst), "l"(src))
#define CP_COMMIT() asm volatile("cp.async.commit_group;")
#define LDSM4(r0, r1, r2, r3, a) \
    asm volatile("ldmatrix.sync.aligned.m8n8.x4.shared.b16 {%0,%1,%2,%3}, [%4];" \
        : "=r"(r0), "=r"(r1), "=r"(r2), "=r"(r3) : "r"(a))
#define MMA_BF16(acc, af, bfr) \
    asm volatile( \
        "mma.sync.aligned.m16n8k16.row.col.f32.bf16.bf16.f32 " \
        "{%0,%1,%2,%3}, {%4,%5,%6,%7}, {%8,%9}, {%0,%1,%2,%3};\n" \
        : "+f"((acc)[0]), "+f"((acc)[1]), "+f"((acc)[2]), "+f"((acc)[3]) \
        : "r"((af)[0]), "r"((af)[1]), "r"((af)[2]), "r"((af)[3]), \
          "r"((bfr)[0]), "r"((bfr)[1]))

#define PSTR 20

// ================= merged fp32->bf16 conversions + mh zero, ONE launch =================
struct CvtArgs {
    const float* src[7];
    __nv_bfloat16* dst[7];
    float* mh;
};

__global__ void cvt_all_kernel(CvtArgs a) {
    if (blockIdx.x >= 7168) {
        for (int j = threadIdx.x; j < PH*PL; j += 256) a.mh[j] = 0.f;
        return;
    }
    const int job = blockIdx.x >> 10;
    const long blk = blockIdx.x & 1023;
    const float* __restrict__ src = a.src[job];
    __nv_bfloat16* __restrict__ dst = a.dst[job];
    const long i = (blk * 256 + threadIdx.x) * 16;
    const float4 v0 = *(const float4*)(src + i);
    const float4 v1 = *(const float4*)(src + i + 4);
    const float4 v2 = *(const float4*)(src + i + 8);
    const float4 v3 = *(const float4*)(src + i + 12);
    uint4 p0, p1;
    p0.x = f2bf2(v0.x, v0.y); p0.y = f2bf2(v0.z, v0.w);
    p0.z = f2bf2(v1.x, v1.y); p0.w = f2bf2(v1.z, v1.w);
    p1.x = f2bf2(v2.x, v2.y); p1.y = f2bf2(v2.z, v2.w);
    p1.z = f2bf2(v3.x, v3.y); p1.w = f2bf2(v3.z, v3.w);
    *(uint4*)(dst + i) = p0;
    *(uint4*)(dst + i + 8) = p1;
}

// ================= big bf16 GEMM core (256x128 tile, 512 threads) =================
#define STGA (256*PSTR)
#define STGB (128*PSTR)
#define NSTB 6
#define BIG_SMEM (NSTB*(STGA + STGB)*4)   // 184320

// Merged Q/K/V projection: blockIdx.z selects operand set + epilogue.
// z=0: Q fp32 permute; z=1: K bf16 + phi(K) bf16; z=2: V bf16.
__global__ __launch_bounds__(512, 1)
void big3_gemm(const __nv_bfloat16* __restrict__ qbf, const __nv_bfloat16* __restrict__ kbf,
               const __nv_bfloat16* __restrict__ vbf,
               const __nv_bfloat16* __restrict__ wq, const __nv_bfloat16* __restrict__ wk,
               const __nv_bfloat16* __restrict__ wv,
               float* __restrict__ Qo, __nv_bfloat16* __restrict__ kbhl,
               __nv_bfloat16* __restrict__ pk, __nv_bfloat16* __restrict__ vbhl)
{
    extern __shared__ __align__(16) uint32_t sm[];
    const uint32_t sbase = smem_u32(sm);

    const int z = blockIdx.z;
    const __nv_bfloat16* __restrict__ Ag = (z == 0) ? qbf : (z == 1) ? kbf : vbf;
    const __nv_bfloat16* __restrict__ Wg = (z == 0) ? wq  : (z == 1) ? wk  : wv;

    const int tid = threadIdx.x;
    const int lane = tid & 31;
    const int warpId = tid >> 5;
    const int g = lane >> 2;
    const int t = lane & 3;
    const int warpM = warpId >> 2;
    const int warpN = warpId & 3;
    const int m0 = blockIdx.y * 256;
    const int n0 = blockIdx.x * 128;

    const int ga0 = tid, ga1 = tid + 512;
    const int ar0 = ga0 >> 2, ac0 = ga0 & 3;
    const int ar1 = ga1 >> 2, ac1 = ga1 & 3;
    const int br  = tid >> 2, bc = tid & 3;
    const uint32_t da0 = (ar0 * PSTR + ac0 * 4) * 4;
    const uint32_t da1 = (ar1 * PSTR + ac1 * 4) * 4;
    const uint32_t db  = (br  * PSTR + bc  * 4) * 4;

    uint32_t aoff[4];
#pragma unroll
    for (int mt = 0; mt < 4; mt++) {
        const int ar = warpM * 64 + mt * 16 + (lane & 15);
        const int ac = (lane >> 4) * 4;
        aoff[mt] = (ar * PSTR + ac) * 4;
    }
    uint32_t boff[2];
#pragma unroll
    for (int p = 0; p < 2; p++) {
        const int brr = warpN * 32 + p * 16 + (lane & 7) + ((lane >> 4) << 3);
        const int bcc = ((lane >> 3) & 1) * 4;
        boff[p] = (brr * PSTR + bcc) * 4;
    }

    float acc[4][4][4];
#pragma unroll
    for (int mt = 0; mt < 4; mt++)
#pragma unroll
        for (int nt = 0; nt < 4; nt++)
#pragma unroll
            for (int i = 0; i < 4; i++) acc[mt][nt][i] = 0.f;

    auto issue = [&](int s) {
        const int st = s % NSTB;
        const uint32_t aT = sbase + st * STGA * 4;
        const uint32_t bT = sbase + (NSTB * STGA + st * STGB) * 4;
        const int k0 = s * 32;
        CP_ASYNC16(aT + da0, Ag + (long)(m0 + ar0) * PD + k0 + ac0 * 8);
        CP_ASYNC16(aT + da1, Ag + (long)(m0 + ar1) * PD + k0 + ac1 * 8);
        CP_ASYNC16(bT + db,  Wg + (long)(n0 + br)  * PD + k0 + bc  * 8);
        CP_COMMIT();
    };

    const int NSTAGE = PD / 32;
    issue(0); issue(1); issue(2);

    for (int s = 0; s < NSTAGE; s++) {
        if (s + 3 < NSTAGE) { issue(s + 3); asm volatile("cp.async.wait_group 3;"); }
        else if (s + 2 < NSTAGE) { asm volatile("cp.async.wait_group 2;"); }
        else if (s + 1 < NSTAGE) { asm volatile("cp.async.wait_group 1;"); }
        else { asm volatile("cp.async.wait_group 0;"); }
        __syncthreads();

        const int st = s % NSTB;
        const uint32_t aT = sbase + st * STGA * 4;
        const uint32_t bT = sbase + (NSTB * STGA + st * STGB) * 4;

#pragma unroll
        for (int kk = 0; kk < 16; kk += 8) {
            uint32_t af[4][4];
#pragma unroll
            for (int mt = 0; mt < 4; mt++)
                LDSM4(af[mt][0], af[mt][1], af[mt][2], af[mt][3], aT + aoff[mt] + kk * 4);
            uint32_t bfr[4][2];
#pragma unroll
            for (int p = 0; p < 2; p++)
                LDSM4(bfr[2*p][0], bfr[2*p][1], bfr[2*p+1][0], bfr[2*p+1][1],
                      bT + boff[p] + kk * 4);
#pragma unroll
            for (int mt = 0; mt < 4; mt++)
#pragma unroll
                for (int nt = 0; nt < 4; nt++)
                    MMA_BF16(acc[mt][nt], af[mt], bfr[nt]);
        }
    }

#pragma unroll
    for (int mt = 0; mt < 4; mt++) {
        const int rL = m0 + warpM*64 + mt*16 + g;
        const int rH = rL + 8;
#pragma unroll
        for (int nt = 0; nt < 4; nt++) {
            const int c = n0 + warpN*32 + nt*8 + t*2;
            float2 vL = make_float2(acc[mt][nt][0], acc[mt][nt][1]);
            float2 vH = make_float2(acc[mt][nt][2], acc[mt][nt][3]);
            const int h = c >> 8, d = c & 255;
            const int bL = rL >> 8, lL = rL & 255;
            const int bR = rH >> 8, lH = rH & 255;
            const long iL = (((long)(bL*PH + h))*PL + lL)*PDH + d;
            const long iH = (((long)(bR*PH + h))*PL + lH)*PDH + d;
            if (z == 0) {
                *(float2*)&Qo[iL] = vL;
                *(float2*)&Qo[iH] = vH;
            } else if (z == 1) {
                ((uint32_t*)kbhl)[iL >> 1] = f2bf2(vL.x, vL.y);
                ((uint32_t*)kbhl)[iH >> 1] = f2bf2(vH.x, vH.y);
                ((uint32_t*)pk)[iL >> 1] = f2bf2(phif(vL.x), phif(vL.y));
                ((uint32_t*)pk)[iH >> 1] = f2bf2(phif(vH.x), phif(vH.y));
            } else {
                ((uint32_t*)vbhl)[iL >> 1] = f2bf2(vL.x, vL.y);
                ((uint32_t*)vbhl)[iH >> 1] = f2bf2(vH.x, vH.y);
            }
        }
    }
}

// Output projection: o = attn @ Wo^T + bo (fp32 row-major)
__global__ __launch_bounds__(512, 1)
void bigo_gemm(const __nv_bfloat16* __restrict__ Ag, const __nv_bfloat16* __restrict__ Wg,
               float* __restrict__ Cg, const float* __restrict__ bias)
{
    extern __shared__ __align__(16) uint32_t sm[];
    const uint32_t sbase = smem_u32(sm);

    const int tid = threadIdx.x;
    const int lane = tid & 31;
    const int warpId = tid >> 5;
    const int g = lane >> 2;
    const int t = lane & 3;
    const int warpM = warpId >> 2;
    const int warpN = warpId & 3;
    const int m0 = blockIdx.y * 256;
    const int n0 = blockIdx.x * 128;

    const int ga0 = tid, ga1 = tid + 512;
    const int ar0 = ga0 >> 2, ac0 = ga0 & 3;
    const int ar1 = ga1 >> 2, ac1 = ga1 & 3;
    const int br  = tid >> 2, bc = tid & 3;
    const uint32_t da0 = (ar0 * PSTR + ac0 * 4) * 4;
    const uint32_t da1 = (ar1 * PSTR + ac1 * 4) * 4;
    const uint32_t db  = (br  * PSTR + bc  * 4) * 4;

    uint32_t aoff[4];
#pragma unroll
    for (int mt = 0; mt < 4; mt++) {
        const int ar = warpM * 64 + mt * 16 + (lane & 15);
        const int ac = (lane >> 4) * 4;
        aoff[mt] = (ar * PSTR + ac) * 4;
    }
    uint32_t boff[2];
#pragma unroll
    for (int p = 0; p < 2; p++) {
        const int brr = warpN * 32 + p * 16 + (lane & 7) + ((lane >> 4) << 3);
        const int bcc = ((lane >> 3) & 1) * 4;
        boff[p] = (brr * PSTR + bcc) * 4;
    }

    float acc[4][4][4];
#pragma unroll
    for (int mt = 0; mt < 4; mt++)
#pragma unroll
        for (int nt = 0; nt < 4; nt++)
#pragma unroll
            for (int i = 0; i < 4; i++) acc[mt][nt][i] = 0.f;

    auto issue = [&](int s) {
        const int st = s % NSTB;
        const uint32_t aT = sbase + st * STGA * 4;
        const uint32_t bT = sbase + (NSTB * STGA + st * STGB) * 4;
        const int k0 = s * 32;
        CP_ASYNC16(aT + da0, Ag + (long)(m0 + ar0) * PD + k0 + ac0 * 8);
        CP_ASYNC16(aT + da1, Ag + (long)(m0 + ar1) * PD + k0 + ac1 * 8);
        CP_ASYNC16(bT + db,  Wg + (long)(n0 + br)  * PD + k0 + bc  * 8);
        CP_COMMIT();
    };

    const int NSTAGE = PD / 32;
    issue(0); issue(1); issue(2);

    for (int s = 0; s < NSTAGE; s++) {
        if (s + 3 < NSTAGE) { issue(s + 3); asm volatile("cp.async.wait_group 3;"); }
        else if (s + 2 < NSTAGE) { asm volatile("cp.async.wait_group 2;"); }
        else if (s + 1 < NSTAGE) { asm volatile("cp.async.wait_group 1;"); }
        else { asm volatile("cp.async.wait_group 0;"); }
        __syncthreads();

        const int st = s % NSTB;
        const uint32_t aT = sbase + st * STGA * 4;
        const uint32_t bT = sbase + (NSTB * STGA + st * STGB) * 4;

#pragma unroll
        for (int kk = 0; kk < 16; kk += 8) {
            uint32_t af[4][4];
#pragma unroll
            for (int mt = 0; mt < 4; mt++)
                LDSM4(af[mt][0], af[mt][1], af[mt][2], af[mt][3], aT + aoff[mt] + kk * 4);
            uint32_t bfr[4][2];
#pragma unroll
            for (int p = 0; p < 2; p++)
                LDSM4(bfr[2*p][0], bfr[2*p][1], bfr[2*p+1][0], bfr[2*p+1][1],
                      bT + boff[p] + kk * 4);
#pragma unroll
            for (int mt = 0; mt < 4; mt++)
#pragma unroll
                for (int nt = 0; nt < 4; nt++)
                    MMA_BF16(acc[mt][nt], af[mt], bfr[nt]);
        }
    }

#pragma unroll
    for (int mt = 0; mt < 4; mt++) {
        const int rL = m0 + warpM*64 + mt*16 + g;
        const int rH = rL + 8;
#pragma unroll
        for (int nt = 0; nt < 4; nt++) {
            const int c = n0 + warpN*32 + nt*8 + t*2;
            float2 bv = *(const float2*)&bias[c];
            *(float2*)&Cg[(long)rL*PD + c] = make_float2(acc[mt][nt][0] + bv.x, acc[mt][nt][1] + bv.y);
            *(float2*)&Cg[(long)rH*PD + c] = make_float2(acc[mt][nt][2] + bv.x, acc[mt][nt][3] + bv.y);
        }
    }
}

// ================= batched bf16 TN GEMM =================
#define BSTG (128*PSTR)
#define NSTS 4
#define BAT_SMEM (2*NSTS*BSTG*4)

template<int EPI>
__global__ __launch_bounds__(256, 2)
void bat_gemm(const __nv_bfloat16* __restrict__ Ag, const __nv_bfloat16* __restrict__ Bg,
              float* __restrict__ Cg, float* __restrict__ mhp,
              int N, int lda, int ldb,
              long strideA, long strideB, long strideC)
{
    extern __shared__ __align__(16) uint32_t sm[];
    const uint32_t sbase = smem_u32(sm);
    __shared__ float colsum[128];

    const int tid = threadIdx.x;
    const int lane = tid & 31;
    const int warpId = tid >> 5;
    const int g = lane >> 2;
    const int t = lane & 3;
    const int warpM = warpId >> 2;
    const int warpN = warpId & 3;
    const int m0 = blockIdx.y * 128;
    const int n0 = blockIdx.x * 128;
    const int z  = blockIdx.z;
    const __nv_bfloat16* A  = Ag + (long)z * strideA;
    const __nv_bfloat16* Bm = Bg + (long)z * strideB;

    if (EPI == 1) {
        if (tid < 128) colsum[tid] = 0.f;
    }

    const int gid0 = tid, gid1 = tid + 256;
    const int row0 = gid0 >> 2, gc0 = gid0 & 3;
    const int row1 = gid1 >> 2, gc1 = gid1 & 3;
    const uint32_t d0 = (row0 * PSTR + gc0 * 4) * 4;
    const uint32_t d1 = (row1 * PSTR + gc1 * 4) * 4;

    uint32_t aoff[4];
#pragma unroll
    for (int mt = 0; mt < 4; mt++) {
        const int ar = warpM * 64 + mt * 16 + (lane & 15);
        const int ac = (lane >> 4) * 4;
        aoff[mt] = (ar * PSTR + ac) * 4;
    }
    uint32_t boff[2];
#pragma unroll
    for (int p = 0; p < 2; p++) {
        const int br = warpN * 32 + p * 16 + (lane & 7) + ((lane >> 4) << 3);
        const int bc = ((lane >> 3) & 1) * 4;
        boff[p] = (br * PSTR + bc) * 4;
    }

    float acc[4][4][4];
#pragma unroll
    for (int mt = 0; mt < 4; mt++)
#pragma unroll
        for (int nt = 0; nt < 4; nt++)
#pragma unroll
            for (int i = 0; i < 4; i++) acc[mt][nt][i] = 0.f;

    float denL[4] = {0.f,0.f,0.f,0.f};
    float denH[4] = {0.f,0.f,0.f,0.f};

    auto issue = [&](int s) {
        const int st = s & (NSTS - 1);
        const uint32_t aT = sbase + st * BSTG * 4;
        const uint32_t bT = sbase + (NSTS + st) * BSTG * 4;
        const int k0 = s * 32;
        CP_ASYNC16(aT + d0, A  + (long)(m0 + row0) * lda + k0 + gc0 * 8);
        CP_ASYNC16(aT + d1, A  + (long)(m0 + row1) * lda + k0 + gc1 * 8);
        CP_ASYNC16(bT + d0, Bm + (long)(n0 + row0) * ldb + k0 + gc0 * 8);
        CP_ASYNC16(bT + d1, Bm + (long)(n0 + row1) * ldb + k0 + gc1 * 8);
        CP_COMMIT();
    };

    const int NSTAGE = 256 / 32;
    issue(0);
    issue(1);

    for (int s = 0; s < NSTAGE; s++) {
        if (s + 2 < NSTAGE) { issue(s + 2); asm volatile("cp.async.wait_group 2;"); }
        else if (s + 1 < NSTAGE) { asm volatile("cp.async.wait_group 1;"); }
        else { asm volatile("cp.async.wait_group 0;"); }
        __syncthreads();

        const int st = s & (NSTS - 1);
        const uint32_t aT = sbase + st * BSTG * 4;
        const uint32_t bT = sbase + (NSTS + st) * BSTG * 4;

#pragma unroll
        for (int kk = 0; kk < 16; kk += 8) {
            uint32_t af[4][4];
#pragma unroll
            for (int mt = 0; mt < 4; mt++)
                LDSM4(af[mt][0], af[mt][1], af[mt][2], af[mt][3], aT + aoff[mt] + kk * 4);
            uint32_t bfr[4][2];
#pragma unroll
            for (int p = 0; p < 2; p++)
                LDSM4(bfr[2*p][0], bfr[2*p][1], bfr[2*p+1][0], bfr[2*p+1][1],
                      bT + boff[p] + kk * 4);
            if (EPI == 3) {
#pragma unroll
                for (int mt = 0; mt < 4; mt++) {
                    float2 u0 = bf2f(af[mt][0]), u2 = bf2f(af[mt][2]);
                    float2 u1 = bf2f(af[mt][1]), u3 = bf2f(af[mt][3]);
                    denL[mt] += u0.x + u0.y + u2.x + u2.y;
                    denH[mt] += u1.x + u1.y + u3.x + u3.y;
                }
            }
#pragma unroll
            for (int mt = 0; mt < 4; mt++)
#pragma unroll
                for (int nt = 0; nt < 4; nt++)
                    MMA_BF16(acc[mt][nt], af[mt], bfr[nt]);
        }
    }

    float invL[4], invH[4];
    if (EPI == 3) {
#pragma unroll
        for (int mt = 0; mt < 4; mt++) {
            float dl = denL[mt], dh = denH[mt];
            dl += __shfl_xor_sync(0xffffffffu, dl, 1);
            dl += __shfl_xor_sync(0xffffffffu, dl, 2);
            dh += __shfl_xor_sync(0xffffffffu, dh, 1);
            dh += __shfl_xor_sync(0xffffffffu, dh, 2);
            invL[mt] = 1.0f / fmaxf(dl, 1e-8f);
            invH[mt] = 1.0f / fmaxf(dh, 1e-8f);
        }
    }
    if (EPI == 1) __syncthreads();

#pragma unroll
    for (int mt = 0; mt < 4; mt++) {
        const int rL = m0 + warpM*64 + mt*16 + g;
        const int rH = rL + 8;
#pragma unroll
        for (int nt = 0; nt < 4; nt++) {
            const int c = n0 + warpN*32 + nt*8 + t*2;
            float2 vL = make_float2(acc[mt][nt][0], acc[mt][nt][1]);
            float2 vH = make_float2(acc[mt][nt][2], acc[mt][nt][3]);
            if (EPI == 1) {
                float* cz = Cg + (long)z * strideC;
                *(float2*)&cz[(long)rL*N + c] = vL;
                *(float2*)&cz[(long)rH*N + c] = vH;
            } else if (EPI == 2) {
                uint32_t* cz = (uint32_t*)Cg + ((long)z * strideC >> 1);
                const float wLx = c   <= rL ? vL.x : 0.f;
                const float wLy = c+1 <= rL ? vL.y : 0.f;
                const float wHx = c   <= rH ? vH.x : 0.f;
                const float wHy = c+1 <= rH ? vH.y : 0.f;
                cz[((long)rL*N + c) >> 1] = f2bf2(wLx, wLy);
                cz[((long)rH*N + c) >> 1] = f2bf2(wHx, wHy);
            } else {
                const int b = z / PH, h = z % PH;
                uint32_t* cb16 = (uint32_t*)Cg;
                const long iL = ((long)(b*PL + rL))*PD + h*PDH + c;
                const long iH = ((long)(b*PL + rH))*PD + h*PDH + c;
                cb16[iL >> 1] = f2bf2(vL.x*invL[mt], vL.y*invL[mt]);
                cb16[iH >> 1] = f2bf2(vH.x*invH[mt], vH.y*invH[mt]);
            }
        }
    }

    if (EPI == 1) {
#pragma unroll
        for (int nt = 0; nt < 4; nt++) {
            float s0 = 0.f, s1 = 0.f;
#pragma unroll
            for (int mt = 0; mt < 4; mt++) {
                s0 += acc[mt][nt][0] + acc[mt][nt][2];
                s1 += acc[mt][nt][1] + acc[mt][nt][3];
            }
            const int cl = warpN*32 + nt*8 + t*2;
            atomicAdd(&colsum[cl],   s0);
            atomicAdd(&colsum[cl+1], s1);
        }
        __syncthreads();
        if (tid < 128) {
            const int h = z & 7;
            atomicAdd(&mhp[h*PL + n0 + tid], colsum[tid] * (1.0f / (float)(PB*PL)));
        }
    }
}

// ================= V transpose =================
__global__ void vt_kernel(const __nv_bfloat16* __restrict__ in, __nv_bfloat16* __restrict__ out) {
    __shared__ __nv_bfloat16 tile[32][33];
    const int z = blockIdx.z;
    const int l0 = blockIdx.x * 32;
    const int d0 = blockIdx.y * 32;
    const int tx = threadIdx.x, ty = threadIdx.y;
    const __nv_bfloat16* src = in + (long)z * PL * PDH;
    __nv_bfloat16* dst = out + (long)z * PDH * PL;
#pragma unroll
    for (int j = 0; j < 4; j++)
        tile[ty*4 + j][tx] = src[(long)(l0 + ty*4 + j) * PDH + d0 + tx];
    __syncthreads();
#pragma unroll
    for (int j = 0; j < 4; j++)
        dst[(long)(d0 + ty*4 + j) * PL + l0 + tx] = tile[tx][ty*4 + j];
}

// ---------------- small kernels ----------------
__global__ void cs_kernel(const float* __restrict__ mh, float* __restrict__ cs,
                          const float* __restrict__ alpha_p, const float* __restrict__ beta_p) {
    const int d = threadIdx.x;
    const float a = *alpha_p, bt = *beta_p;
    float c = 0.f;
    for (int h = 0; h < PH; h++) {
        cs[h*PDH + d] = c;
        c = bt * c + a * mh[h*PL + d];
    }
}

__global__ void phi_kernel(const float* __restrict__ Q,
                           const float* __restrict__ kv, const float* __restrict__ cs,
                           __nv_bfloat16* __restrict__ pq,
                           const float* __restrict__ alpha_p) {
    const long gid = (long)blockIdx.x * blockDim.x + threadIdx.x;
    const long idx = gid * 2;
    const float a = *alpha_p;
    const int h = (int)((idx >> 16) & 7);
    const int d = (int)(idx & 255);
    const float2 q2 = *(const float2*)(Q + idx);
    const float2 v2 = *(const float2*)(kv + idx);
    const float c0 = cs[h*PDH + d], c1 = cs[h*PDH + d + 1];
    const float qm0 = q2.x * (c0 + a * (v2.x - c0));
    const float qm1 = q2.y * (c1 + a * (v2.y - c1));
    ((uint32_t*)pq)[gid] = f2bf2(phif(qm0), phif(qm1));
}

__global__ void ln_kernel(const float* __restrict__ q, const float* __restrict__ o,
                          const float* __restrict__ g, const float* __restrict__ be,
                          float* __restrict__ out) {
    const int tk = blockIdx.x;
    const int tid = threadIdx.x;
    __shared__ float red[256];
    const float* xq = q + (long)tk * PD;
    const float* xo = o + (long)tk * PD;
    float x[8];
    float s = 0.f;
#pragma unroll
    for (int i = 0; i < 8; i++) {
        x[i] = xq[tid + i*256] + xo[tid + i*256];
        s += x[i];
    }
    red[tid] = s; __syncthreads();
    for (int st = 128; st > 0; st >>= 1) {
        if (tid < st) red[tid] += red[tid + st];
        __syncthreads();
    }
    const float mu = red[0] * (1.0f / PD);
    __syncthreads();
    float v = 0.f;
#pragma unroll
    for (int i = 0; i < 8; i++) { const float dd = x[i] - mu; v += dd*dd; }
    red[tid] = v; __syncthreads();
    for (int st = 128; st > 0; st >>= 1) {
        if (tid < st) red[tid] += red[tid + st];
        __syncthreads();
    }
    const float inv = rsqrtf(red[0] * (1.0f / PD) + 1e-5f);
#pragma unroll
    for (int i = 0; i < 8; i++) {
        const int c = tid + i*256;
        out[(long)tk*PD + c] = (x[i] - mu) * inv * g[c] + be[c];
    }
}

// ---------------- launch ----------------
extern "C" void kernel_launch(void* const* d_in, const int* in_sizes, int n_in,
                              void* d_out, int out_size) {
    const float* query = (const float*)d_in[0];
    const float* key   = (const float*)d_in[1];
    const float* value = (const float*)d_in[2];
    const float* Wq    = (const float*)d_in[3];
    const float* Wk    = (const float*)d_in[4];
    const float* Wv    = (const float*)d_in[5];
    const float* Wo    = (const float*)d_in[6];
    const float* bo    = (const float*)d_in[7];
    const float* ln_g  = (const float*)d_in[8];
    const float* ln_b  = (const float*)d_in[9];
    const float* alpha = (const float*)d_in[10];
    const float* beta  = (const float*)d_in[11];
    float* out = (float*)d_out;

    float *Q, *kv, *o, *mh, *cs;
    __nv_bfloat16 *kbhl, *vbhl, *vt, *pq, *pk, *Am, *attnbf;
    __nv_bfloat16 *qbf, *kbf, *vbf, *wqbf, *wkbf, *wvbf, *wobf;
    cudaGetSymbolAddress((void**)&Q,  g_Q);
    cudaGetSymbolAddress((void**)&kv, g_kv);
    cudaGetSymbolAddress((void**)&o,  g_o);
    cudaGetSymbolAddress((void**)&mh, g_mh);
    cudaGetSymbolAddress((void**)&cs, g_cs);
    cudaGetSymbolAddress((void**)&kbhl, g_kbhl);
    cudaGetSymbolAddress((void**)&vbhl, g_vbhl);
    cudaGetSymbolAddress((void**)&vt, g_vt);
    cudaGetSymbolAddress((void**)&pq, g_pq);
    cudaGetSymbolAddress((void**)&pk, g_pk);
    cudaGetSymbolAddress((void**)&Am, g_Am);
    cudaGetSymbolAddress((void**)&attnbf, g_attnbf);
    cudaGetSymbolAddress((void**)&qbf, g_qbf);
    cudaGetSymbolAddress((void**)&kbf, g_kbf);
    cudaGetSymbolAddress((void**)&vbf, g_vbf);
    cudaGetSymbolAddress((void**)&wqbf, g_wqbf);
    cudaGetSymbolAddress((void**)&wkbf, g_wkbf);
    cudaGetSymbolAddress((void**)&wvbf, g_wvbf);
    cudaGetSymbolAddress((void**)&wobf, g_wobf);

    cudaFuncSetAttribute(big3_gemm, cudaFuncAttributeMaxDynamicSharedMemorySize, BIG_SMEM);
    cudaFuncSetAttribute(bigo_gemm, cudaFuncAttributeMaxDynamicSharedMemorySize, BIG_SMEM);
    cudaFuncSetAttribute(bat_gemm<1>, cudaFuncAttributeMaxDynamicSharedMemorySize, BAT_SMEM);
    cudaFuncSetAttribute(bat_gemm<2>, cudaFuncAttributeMaxDynamicSharedMemorySize, BAT_SMEM);
    cudaFuncSetAttribute(bat_gemm<3>, cudaFuncAttributeMaxDynamicSharedMemorySize, BAT_SMEM);

    dim3 gBig3(PD/128, PT/256, 3);          // 16 x 8 x 3 = 384 CTAs
    dim3 gBigO(PD/128, PT/256, 1);
    dim3 gBat(2, 2, BH);

    // 1. all conversions + mh zero, one launch
    CvtArgs ca;
    ca.src[0] = query; ca.dst[0] = qbf;
    ca.src[1] = key;   ca.dst[1] = kbf;
    ca.src[2] = value; ca.dst[2] = vbf;
    ca.src[3] = Wq;    ca.dst[3] = wqbf;
    ca.src[4] = Wk;    ca.dst[4] = wkbf;
    ca.src[5] = Wv;    ca.dst[5] = wvbf;
    ca.src[6] = Wo;    ca.dst[6] = wobf;
    ca.mh = mh;
    cvt_all_kernel<<<7169, 256>>>(ca);

    // 2. merged Q/K/V projections (one launch, z selects)
    big3_gemm<<<gBig3, 512, BIG_SMEM>>>(qbf, kbf, vbf, wqbf, wkbf, wvbf,
                                        Q, kbhl, pk, vbhl);

    // 3. kv = K @ V^T + fused column-mean -> mh
    bat_gemm<1><<<gBat, 256, BAT_SMEM>>>(kbhl, vbhl, kv, mh, PL, PDH, PDH,
                                         (long)PL*PDH, (long)PL*PDH, (long)PL*PL);

    // 4. cs scan
    cs_kernel<<<1, 256>>>(mh, cs, alpha, beta);

    // 5. pq
    phi_kernel<<<(BH*PL*PDH/2) / 256, 256>>>(Q, kv, cs, pq, alpha);

    // 6. A = tril(pq @ pk^T) -> bf16  (this is ncu launch #6)
    bat_gemm<2><<<gBat, 256, BAT_SMEM>>>(pq, pk, (float*)Am, nullptr, PL, PDH, PDH,
                                         (long)PL*PDH, (long)PL*PDH, (long)PL*PL);

    // 7. V transpose
    vt_kernel<<<dim3(PL/32, PDH/32, BH), dim3(32, 8)>>>(vbhl, vt);

    // 8. attn = (A @ V) / rowsum(A) -> bf16 (B,L,D)
    bat_gemm<3><<<gBat, 256, BAT_SMEM>>>(Am, vt, (float*)attnbf, nullptr, PDH, PL, PL,
                                         (long)PL*PL, (long)PDH*PL, 0);

    // 9. o = attn @ Wo^T + bo
    bigo_gemm<<<gBigO, 512, BIG_SMEM>>>(attnbf, wobf, o, bo);

    // 10. residual + layernorm
    ln_kernel<<<PT, 256>>>(query, o, ln_g, ln_b, out);
}